// round 9
// baseline (speedup 1.0000x reference)
#include <cuda_runtime.h>
#include <math.h>
#include <stdint.h>

// Problem constants
#define B_      64
#define N1_     512
#define N2_     512
#define NPER    1024
#define NTOT    65536
#define KSEL    256
#define NPOOL   16384
#define E_ALL   1048576
#define E_C     524288

// ---------------- scratch ----------------
__device__ float g_h0[(size_t)NTOT * 128];
__device__ float g_h1[(size_t)NTOT * 128];
__device__ float g_h2[(size_t)NTOT * 128];
__device__ float g_xw[(size_t)NTOT * 128];
__device__ float g_dis[NTOT];

// CSR for the big graph
__device__ int g_degI[NTOT];
__device__ int g_rowstart[NTOT];
__device__ int g_cursor[NTOT];
__device__ int g_ecol[E_ALL];
__device__ int g_ctr[2];

__device__ float g_mean[128 * 384];
__device__ float g_catt[128 * 384];
__device__ float g_gp[128 * 384];
__device__ float g_pv[64 * 768];
__device__ float g_pvnorm[128];

__device__ float g_score[2][B_ * N1_];
__device__ int   g_map[2][B_ * N1_];
__device__ int   g_perm[2][B_ * KSEL];
__device__ float g_pool[2][(size_t)NPOOL * 384];

// pooled CSR (combined over both clusters)
__device__ int   g_degPI[2 * NPOOL];
__device__ int   g_rowstartP[2 * NPOOL];
__device__ int   g_cursorP[2 * NPOOL];
__device__ int   g_ecolP[2 * E_C];
__device__ float g_disP[2 * NPOOL];

__device__ float g_xwP[(size_t)2 * NPOOL * 128];
__device__ float g_hP[2][(size_t)NPOOL * 128];

__device__ float g_meanF[2][B_ * 128];
__device__ float g_cF[2][B_ * 128];
__device__ float g_alphaP[2][NPOOL];
__device__ float g_gfin[2][B_ * 128];

__device__ __forceinline__ float xcat_at(int node, int f) {
    const float* H = (f < 128) ? g_h0 : ((f < 256) ? g_h1 : g_h2);
    return H[(size_t)node * 128 + (f & 127)];
}
__device__ __forceinline__ float sigmoidf_(float x) { return 1.f / (1.f + expf(-x)); }

// ---------------- zero everything that accumulates ----------------
__global__ void zero_all_kernel() {
    const int NM = 128 * 384;
    int stride = gridDim.x * blockDim.x;
    for (int i = blockIdx.x * blockDim.x + threadIdx.x;
         i < NTOT + 2 * NPOOL + 2 + 2 * NM + 2 * 2 * B_ * 128; i += stride) {
        int j = i;
        if (j < NTOT) { g_degI[j] = 0; continue; }
        j -= NTOT;
        if (j < 2 * NPOOL) { g_degPI[j] = 0; continue; }
        j -= 2 * NPOOL;
        if (j < 2) { g_ctr[j] = 0; continue; }
        j -= 2;
        if (j < NM) { g_mean[j] = 0.f; continue; }
        j -= NM;
        if (j < NM) { g_gp[j] = 0.f; continue; }
        j -= NM;
        if (j < 2 * B_ * 128) { ((float*)g_meanF)[j] = 0.f; continue; }
        j -= 2 * B_ * 128;
        ((float*)g_gfin)[j] = 0.f;
    }
}

__global__ void degi_kernel(const int* __restrict__ dst, int* __restrict__ deg, int E) {
    int e = blockIdx.x * blockDim.x + threadIdx.x;
    if (e < E) atomicAdd(&deg[dst[e]], 1);
}
__global__ void degPI_kernel(const int* __restrict__ src, const int* __restrict__ dst,
                             const int* __restrict__ map, int* __restrict__ deg, int E) {
    int e = blockIdx.x * blockDim.x + threadIdx.x;
    if (e >= E) return;
    int r = map[src[e]], c = map[dst[e]];
    if (r >= 0 && c >= 0) atomicAdd(&deg[c], 1);
}

// rowstart assignment without scans: order-free atomic range grab.
// Also initializes cursor (=rowstart) and dis (=rsqrt(deg+1)).
__global__ void assign_kernel(const int* __restrict__ deg, int* __restrict__ rowstart,
                              int* __restrict__ cursor, float* __restrict__ dis,
                              int n, int* __restrict__ ctr) {
    int i = blockIdx.x * blockDim.x + threadIdx.x;
    if (i >= n) return;
    int d = deg[i];
    int rs = atomicAdd(ctr, d);
    rowstart[i] = rs;
    cursor[i] = rs;
    dis[i] = rsqrtf((float)d + 1.f);
}

// ---------------- CSR edge placement (cursor pre-seeded with rowstart) ----------------
__global__ void place_kernel(const int* __restrict__ src, const int* __restrict__ dst,
                             int* __restrict__ cursor, int* __restrict__ ecol, int E) {
    int e = blockIdx.x * blockDim.x + threadIdx.x;
    if (e >= E) return;
    int pos = atomicAdd(&cursor[dst[e]], 1);
    ecol[pos] = src[e];
}
__global__ void placeP_kernel(const int* __restrict__ src, const int* __restrict__ dst,
                              const int* __restrict__ map,
                              int* __restrict__ cursor, int* __restrict__ ecol, int E, int off) {
    int e = blockIdx.x * blockDim.x + threadIdx.x;
    if (e >= E) return;
    int r = map[src[e]], c = map[dst[e]];
    if (r < 0 || c < 0) return;
    int pos = atomicAdd(&cursor[c + off], 1);
    ecol[pos] = r + off;
}

// ============ 3xTF32 tensor-core GEMM, hi/lo interleaved smem ============
// x = hi + lo (both tf32); acc += aL*bH + aH*bL + aH*bH  (~2^-22 effective precision)
__device__ __forceinline__ uint32_t f2tf32(float x) {
    uint32_t y;
    asm("cvt.rna.tf32.f32 %0, %1;" : "=r"(y) : "f"(x));
    return y;
}
__device__ __forceinline__ void mma_tf32(float* c, const uint32_t* a, uint32_t b0, uint32_t b1) {
    asm volatile("mma.sync.aligned.m16n8k8.row.col.f32.tf32.tf32.f32 "
                 "{%0,%1,%2,%3}, {%4,%5,%6,%7}, {%8,%9}, {%0,%1,%2,%3};"
                 : "+f"(c[0]), "+f"(c[1]), "+f"(c[2]), "+f"(c[3])
                 : "r"(a[0]), "r"(a[1]), "r"(a[2]), "r"(a[3]), "r"(b0), "r"(b1));
}

// interleaved strides in 4B words; both ≡ 8 (mod 32) -> conflict-free LDS.64 fragment loads
#define AS_STRIDE 72    // A row: 32 cols x {hi,lo} = 64 words + 8 pad
#define BS_STRIDE 264   // B row: 128 cols x {hi,lo} = 256 words + 8 pad
#define GEMM_SMEM ((128 * AS_STRIDE + 32 * BS_STRIDE) * 4)   // 70656 bytes

__device__ __forceinline__ void ldg_chunk(const float* __restrict__ A, const float* __restrict__ W,
                                          int K, int R0, int k0, int tid,
                                          float4* ra, float4* rb) {
#pragma unroll
    for (int i = 0; i < 4; i++) {       // A chunk: 128 rows x 32 cols
        int q = tid + i * 256;
        int r = q >> 3, c4 = (q & 7) << 2;
        ra[i] = *(const float4*)(A + (size_t)(R0 + r) * K + k0 + c4);
    }
#pragma unroll
    for (int i = 0; i < 4; i++) {       // W chunk: 32 rows x 128 cols
        int q = tid + i * 256;
        int r = q >> 5, c4 = (q & 31) << 2;
        rb[i] = *(const float4*)(W + (size_t)(k0 + r) * 128 + c4);
    }
}

__device__ __forceinline__ void split2(float v, float2* out) {
    float h = __uint_as_float(f2tf32(v));
    out->x = h;
    out->y = __uint_as_float(f2tf32(v - h));
}

__device__ __forceinline__ void sts_chunk(float* As, float* Bs,
                                          int tid, const float4* ra, const float4* rb) {
#pragma unroll
    for (int i = 0; i < 4; i++) {
        int q = tid + i * 256;
        int r = q >> 3, c4 = (q & 7) << 2;
        float2* p = (float2*)(As + r * AS_STRIDE + c4 * 2);
        split2(ra[i].x, p + 0);
        split2(ra[i].y, p + 1);
        split2(ra[i].z, p + 2);
        split2(ra[i].w, p + 3);
    }
#pragma unroll
    for (int i = 0; i < 4; i++) {
        int q = tid + i * 256;
        int r = q >> 5, c4 = (q & 31) << 2;
        float2* p = (float2*)(Bs + r * BS_STRIDE + c4 * 2);
        split2(rb[i].x, p + 0);
        split2(rb[i].y, p + 1);
        split2(rb[i].z, p + 2);
        split2(rb[i].w, p + 3);
    }
}

__global__ void __launch_bounds__(256, 2) gemm_tf32(
    const float* __restrict__ A, const float* __restrict__ W,
    float* __restrict__ C, int K)
{
    extern __shared__ float sm[];
    float* As = sm;                       // [128][AS_STRIDE] interleaved hi/lo
    float* Bs = sm + 128 * AS_STRIDE;     // [32][BS_STRIDE]

    int tid = threadIdx.x, lane = tid & 31, w = tid >> 5;
    int mw = w >> 1, nw = w & 1;
    int R0 = blockIdx.x * 128;

    float c[2][8][4];
#pragma unroll
    for (int mi = 0; mi < 2; mi++)
#pragma unroll
        for (int ni = 0; ni < 8; ni++)
#pragma unroll
            for (int k = 0; k < 4; k++) c[mi][ni][k] = 0.f;

    float4 ra[4], rb[4];
    ldg_chunk(A, W, K, R0, 0, tid, ra, rb);
    sts_chunk(As, Bs, tid, ra, rb);

    int nch = K >> 5;
    for (int ch = 0; ch < nch; ch++) {
        __syncthreads();
        if (ch + 1 < nch) ldg_chunk(A, W, K, R0, (ch + 1) << 5, tid, ra, rb);
#pragma unroll
        for (int step = 0; step < 4; step++) {
            int kk = step * 8;
            uint32_t aH[2][4], aL[2][4];
#pragma unroll
            for (int mi = 0; mi < 2; mi++) {
                int r = mw * 32 + mi * 16 + (lane >> 2);
                int cc = kk + (lane & 3);
                float2 v0 = *(const float2*)(As + r * AS_STRIDE + cc * 2);
                float2 v1 = *(const float2*)(As + (r + 8) * AS_STRIDE + cc * 2);
                float2 v2 = *(const float2*)(As + r * AS_STRIDE + (cc + 4) * 2);
                float2 v3 = *(const float2*)(As + (r + 8) * AS_STRIDE + (cc + 4) * 2);
                aH[mi][0] = __float_as_uint(v0.x); aL[mi][0] = __float_as_uint(v0.y);
                aH[mi][1] = __float_as_uint(v1.x); aL[mi][1] = __float_as_uint(v1.y);
                aH[mi][2] = __float_as_uint(v2.x); aL[mi][2] = __float_as_uint(v2.y);
                aH[mi][3] = __float_as_uint(v3.x); aL[mi][3] = __float_as_uint(v3.y);
            }
#pragma unroll
            for (int ni = 0; ni < 8; ni++) {
                int n = nw * 64 + ni * 8 + (lane >> 2);
                float2 b0 = *(const float2*)(Bs + (kk + (lane & 3)) * BS_STRIDE + n * 2);
                float2 b1 = *(const float2*)(Bs + (kk + 4 + (lane & 3)) * BS_STRIDE + n * 2);
                uint32_t bH0 = __float_as_uint(b0.x), bL0 = __float_as_uint(b0.y);
                uint32_t bH1 = __float_as_uint(b1.x), bL1 = __float_as_uint(b1.y);
                mma_tf32(c[0][ni], aL[0], bH0, bH1);
                mma_tf32(c[1][ni], aL[1], bH0, bH1);
                mma_tf32(c[0][ni], aH[0], bL0, bL1);
                mma_tf32(c[1][ni], aH[1], bL0, bL1);
                mma_tf32(c[0][ni], aH[0], bH0, bH1);
                mma_tf32(c[1][ni], aH[1], bH0, bH1);
            }
        }
        if (ch + 1 < nch) {
            __syncthreads();
            sts_chunk(As, Bs, tid, ra, rb);
        }
    }

#pragma unroll
    for (int mi = 0; mi < 2; mi++) {
#pragma unroll
        for (int ni = 0; ni < 8; ni++) {
            int row = R0 + mw * 32 + mi * 16 + (lane >> 2);
            int col = nw * 64 + ni * 8 + 2 * (lane & 3);
            *(float2*)(C + (size_t)row * 128 + col) = make_float2(c[mi][ni][0], c[mi][ni][1]);
            *(float2*)(C + (size_t)(row + 8) * 128 + col) = make_float2(c[mi][ni][2], c[mi][ni][3]);
        }
    }
}

// ---------------- CSR gather-aggregate + self loop + bias + relu (4-way unrolled) ----------------
__global__ void __launch_bounds__(256) agg_kernel(
    const float* __restrict__ xw,
    const int* __restrict__ rowstart, const int* __restrict__ degI,
    const int* __restrict__ ecol, const float* __restrict__ dis,
    const float* __restrict__ bias, float* __restrict__ out, int n)
{
    int w = (blockIdx.x * blockDim.x + threadIdx.x) >> 5;
    if (w >= n) return;
    int lane = threadIdx.x & 31;
    int rs = rowstart[w];
    int re = rs + degI[w];
    float4 a0 = make_float4(0.f, 0.f, 0.f, 0.f);
    float4 a1 = make_float4(0.f, 0.f, 0.f, 0.f);
    float4 a2 = make_float4(0.f, 0.f, 0.f, 0.f);
    float4 a3 = make_float4(0.f, 0.f, 0.f, 0.f);
    int i = rs;
    for (; i + 4 <= re; i += 4) {
        int s0 = ecol[i], s1 = ecol[i + 1], s2 = ecol[i + 2], s3 = ecol[i + 3];
        float w0 = dis[s0], w1 = dis[s1], w2 = dis[s2], w3 = dis[s3];
        float4 v0 = *(const float4*)(xw + (size_t)s0 * 128 + lane * 4);
        float4 v1 = *(const float4*)(xw + (size_t)s1 * 128 + lane * 4);
        float4 v2 = *(const float4*)(xw + (size_t)s2 * 128 + lane * 4);
        float4 v3 = *(const float4*)(xw + (size_t)s3 * 128 + lane * 4);
        a0.x = fmaf(v0.x, w0, a0.x); a0.y = fmaf(v0.y, w0, a0.y);
        a0.z = fmaf(v0.z, w0, a0.z); a0.w = fmaf(v0.w, w0, a0.w);
        a1.x = fmaf(v1.x, w1, a1.x); a1.y = fmaf(v1.y, w1, a1.y);
        a1.z = fmaf(v1.z, w1, a1.z); a1.w = fmaf(v1.w, w1, a1.w);
        a2.x = fmaf(v2.x, w2, a2.x); a2.y = fmaf(v2.y, w2, a2.y);
        a2.z = fmaf(v2.z, w2, a2.z); a2.w = fmaf(v2.w, w2, a2.w);
        a3.x = fmaf(v3.x, w3, a3.x); a3.y = fmaf(v3.y, w3, a3.y);
        a3.z = fmaf(v3.z, w3, a3.z); a3.w = fmaf(v3.w, w3, a3.w);
    }
    for (; i < re; i++) {
        int s0 = ecol[i];
        float w0 = dis[s0];
        float4 v0 = *(const float4*)(xw + (size_t)s0 * 128 + lane * 4);
        a0.x = fmaf(v0.x, w0, a0.x); a0.y = fmaf(v0.y, w0, a0.y);
        a0.z = fmaf(v0.z, w0, a0.z); a0.w = fmaf(v0.w, w0, a0.w);
    }
    a0.x += a1.x + a2.x + a3.x;
    a0.y += a1.y + a2.y + a3.y;
    a0.z += a1.z + a2.z + a3.z;
    a0.w += a1.w + a2.w + a3.w;
    float dd = dis[w];
    float sw = dd * dd;
    float4 self = *(const float4*)(xw + (size_t)w * 128 + lane * 4);
    float4 r;
    r.x = fmaxf(fmaf(a0.x, dd, fmaf(self.x, sw, bias[lane * 4 + 0])), 0.f);
    r.y = fmaxf(fmaf(a0.y, dd, fmaf(self.y, sw, bias[lane * 4 + 1])), 0.f);
    r.z = fmaxf(fmaf(a0.z, dd, fmaf(self.z, sw, bias[lane * 4 + 2])), 0.f);
    r.w = fmaxf(fmaf(a0.w, dd, fmaf(self.w, sw, bias[lane * 4 + 3])), 0.f);
    *(float4*)(out + (size_t)w * 128 + lane * 4) = r;
}

// ---------------- attention pool (big, 384 feats) ----------------
__global__ void mean384_kernel() {
    int s = blockIdx.x >> 2, ch = blockIdx.x & 3;
    int f = threadIdx.x;
    int g = s & 63, cl = s >> 6;
    int base = g * NPER + cl * N1_ + ch * 128;
    float acc = 0.f;
#pragma unroll 4
    for (int j = 0; j < 128; j++) acc += xcat_at(base + j, f);
    atomicAdd(&g_mean[s * 384 + f], acc);
}

__global__ void catt_kernel(const float* __restrict__ Wg) {
    __shared__ float m[384];
    int s = blockIdx.x, f = threadIdx.x;
    m[f] = g_mean[s * 384 + f] * (1.f / 512.f);
    __syncthreads();
    float acc = 0.f;
    for (int k = 0; k < 384; k++) acc = fmaf(m[k], Wg[k * 384 + f], acc);
    g_catt[s * 384 + f] = tanhf(acc);
}

// fused alpha + gp: one xcat pass.
__global__ void __launch_bounds__(256) alphagp_kernel() {
    int blk = blockIdx.x;
    int s = blk >> 3, ch = blk & 7;
    int g = s & 63, cl = s >> 6;
    int base = g * NPER + cl * N1_ + ch * 64;
    int wid = threadIdx.x >> 5, lane = threadIdx.x & 31;
    __shared__ float csh[384];
    __shared__ float gpsh[384];
    for (int t = threadIdx.x; t < 384; t += 256) { csh[t] = g_catt[s * 384 + t]; gpsh[t] = 0.f; }
    __syncthreads();
    float acc[12];
#pragma unroll
    for (int q = 0; q < 12; q++) acc[q] = 0.f;
    for (int j = 0; j < 8; j++) {
        int node = base + wid * 8 + j;
        float xv[12];
        float dot = 0.f;
#pragma unroll
        for (int q = 0; q < 12; q++) {
            int f = q * 32 + lane;
            xv[q] = xcat_at(node, f);
            dot = fmaf(xv[q], csh[f], dot);
        }
#pragma unroll
        for (int o = 16; o; o >>= 1) dot += __shfl_xor_sync(0xffffffffu, dot, o);
        float alpha = sigmoidf_(dot);
#pragma unroll
        for (int q = 0; q < 12; q++) acc[q] = fmaf(xv[q], alpha, acc[q]);
    }
#pragma unroll
    for (int q = 0; q < 12; q++) atomicAdd(&gpsh[q * 32 + lane], acc[q]);
    __syncthreads();
    for (int t = threadIdx.x; t < 384; t += 256) atomicAdd(&g_gp[s * 384 + t], gpsh[t]);
}

__global__ void pv_kernel(const float* __restrict__ Wal, const float* __restrict__ bal) {
    __shared__ float in[768];
    int g = blockIdx.x, t = threadIdx.x;
    in[t] = (t < 384) ? g_gp[g * 384 + t] : g_gp[(64 + g) * 384 + (t - 384)];
    __syncthreads();
    float acc = bal[t];
    for (int k = 0; k < 768; k++) acc = fmaf(in[k], Wal[k * 768 + t], acc);
    g_pv[g * 768 + t] = acc;
}

__global__ void pvnorm_kernel() {
    int b = blockIdx.x;
    int cl = b >> 6, g = b & 63;
    int t = threadIdx.x;
    float acc = 0.f;
    for (int k = t; k < 384; k += 128) {
        float v = g_pv[g * 768 + cl * 384 + k];
        acc += v * v;
    }
    __shared__ float red[128];
    red[t] = acc;
    __syncthreads();
    for (int o = 64; o; o >>= 1) {
        if (t < o) red[t] += red[t + o];
        __syncthreads();
    }
    if (!t) g_pvnorm[b] = sqrtf(red[0]);
}

// ---------------- CAG pool ----------------
__global__ void score_kernel() {
    int w = (blockIdx.x * blockDim.x + threadIdx.x) >> 5;
    if (w >= NTOT) return;
    int lane = threadIdx.x & 31;
    int cl = w >> 15;
    int rem = w & 32767;
    int g = rem >> 9, j = rem & 511;
    int node = g * NPER + cl * N1_ + j;
    const float* q = g_pv + g * 768 + cl * 384;
    float acc = 0.f;
    for (int t = lane; t < 384; t += 32) acc += xcat_at(node, t) * q[t];
#pragma unroll
    for (int o = 16; o; o >>= 1) acc += __shfl_xor_sync(0xffffffffu, acc, o);
    if (!lane) g_score[cl][g * 512 + j] = acc / g_pvnorm[cl * 64 + g];
}

__global__ void topk_kernel() {
    int b = blockIdx.x;
    int cl = b >> 6, g = b & 63;
    int j = threadIdx.x;
    __shared__ float s[512];
    s[j] = g_score[cl][g * 512 + j];
    __syncthreads();
    float mys = s[j];
    int rank = 0;
    for (int i = 0; i < 512; i++) {
        float o = s[i];
        rank += (o > mys) || (o == mys && i < j);
    }
    g_map[cl][g * 512 + j] = (rank < KSEL) ? (g * KSEL + rank) : -1;
    if (rank < KSEL) g_perm[cl][g * KSEL + rank] = j;
}

__global__ void gather_kernel() {
    int w = (blockIdx.x * blockDim.x + threadIdx.x) >> 5;
    if (w >= 2 * NPOOL) return;
    int lane = threadIdx.x & 31;
    int cl = w >> 14;
    int r = w & (NPOOL - 1);
    int g = r >> 8;
    int j = g_perm[cl][r];
    int node = g * NPER + cl * N1_ + j;
    float gate = sigmoidf_(g_score[cl][g * 512 + j]);
    float* o = g_pool[cl] + (size_t)r * 384;
    for (int t = lane; t < 384; t += 32) o[t] = xcat_at(node, t) * gate;
}

// ---------------- final attention pool ----------------
__global__ void meanF_kernel() {
    int b = blockIdx.x >> 1, ch = blockIdx.x & 1;
    int cl = b >> 6, g = b & 63;
    int f = threadIdx.x;
    const float* h = g_hP[cl] + ((size_t)g * KSEL + ch * 128) * 128;
    float acc = 0.f;
#pragma unroll 4
    for (int j = 0; j < 128; j++) acc += h[(size_t)j * 128 + f];
    atomicAdd(&g_meanF[cl][g * 128 + f], acc);
}

__global__ void cF_kernel(const float* __restrict__ Wg) {
    int b = blockIdx.x;
    int cl = b >> 6, g = b & 63;
    int f = threadIdx.x;
    __shared__ float m[128];
    m[f] = g_meanF[cl][g * 128 + f] * (1.f / 256.f);
    __syncthreads();
    float acc = 0.f;
    for (int k = 0; k < 128; k++) acc = fmaf(m[k], Wg[k * 128 + f], acc);
    g_cF[cl][g * 128 + f] = tanhf(acc);
}

__global__ void alphaP_kernel() {
    int w = (blockIdx.x * blockDim.x + threadIdx.x) >> 5;
    if (w >= 2 * NPOOL) return;
    int lane = threadIdx.x & 31;
    int cl = w >> 14;
    int r = w & (NPOOL - 1);
    int g = r >> 8;
    const float* h = g_hP[cl] + (size_t)r * 128;
    const float* c = g_cF[cl] + g * 128;
    float acc = 0.f;
    for (int t = lane; t < 128; t += 32) acc += h[t] * c[t];
#pragma unroll
    for (int o = 16; o; o >>= 1) acc += __shfl_xor_sync(0xffffffffu, acc, o);
    if (!lane) g_alphaP[cl][r] = sigmoidf_(acc);
}

__global__ void gfin_kernel() {
    int b = blockIdx.x >> 1, ch = blockIdx.x & 1;
    int cl = b >> 6, g = b & 63;
    int f = threadIdx.x;
    float acc = 0.f;
#pragma unroll 4
    for (int j = 0; j < 128; j++) {
        int r = g * KSEL + ch * 128 + j;
        acc = fmaf(g_hP[cl][(size_t)r * 128 + f], g_alphaP[cl][r], acc);
    }
    atomicAdd(&g_gfin[cl][g * 128 + f], acc);
}

// ---------------- final MLP ----------------
__global__ void mlp_kernel(const float* __restrict__ Wl1, const float* __restrict__ bl1,
                           const float* __restrict__ Wl2, const float* __restrict__ bl2,
                           const float* __restrict__ Wl3, const float* __restrict__ bl3,
                           float* __restrict__ out)
{
    __shared__ float in[256];
    __shared__ float z1[128];
    __shared__ float z2[64];
    int g = blockIdx.x, t = threadIdx.x;
    in[t] = g_gfin[0][g * 128 + t];
    in[128 + t] = g_gfin[1][g * 128 + t];
    __syncthreads();
    float a = bl1[t];
    for (int k = 0; k < 256; k++) a = fmaf(in[k], Wl1[k * 128 + t], a);
    z1[t] = fmaxf(a, 0.f);
    __syncthreads();
    if (t < 64) {
        float a2 = bl2[t];
        for (int k = 0; k < 128; k++) a2 = fmaf(z1[k], Wl2[k * 64 + t], a2);
        z2[t] = fmaxf(a2, 0.f);
    }
    __syncthreads();
    if (t < 2) {
        float a3 = bl3[t];
        for (int k = 0; k < 64; k++) a3 = fmaf(z2[k], Wl3[k * 2 + t], a3);
        out[g * 2 + t] = a3;
    }
}

// ---------------- host orchestration ----------------
extern "C" void kernel_launch(void* const* d_in, const int* in_sizes, int n_in,
                              void* d_out, int out_size)
{
    const float* x       = (const float*)d_in[0];
    const int*   src_all = (const int*)d_in[1];
    const int*   dst_all = (const int*)d_in[2];
    const int*   src_c[2] = { (const int*)d_in[3], (const int*)d_in[5] };
    const int*   dst_c[2] = { (const int*)d_in[4], (const int*)d_in[6] };
    const float* W1 = (const float*)d_in[7];  const float* b1 = (const float*)d_in[8];
    const float* W2 = (const float*)d_in[9];  const float* b2 = (const float*)d_in[10];
    const float* W3 = (const float*)d_in[11]; const float* b3 = (const float*)d_in[12];
    const float* Wg_att = (const float*)d_in[13];
    const float* Wal = (const float*)d_in[14]; const float* bal = (const float*)d_in[15];
    const float* Wf  = (const float*)d_in[16]; const float* bf  = (const float*)d_in[17];
    const float* Wg_fin = (const float*)d_in[18];
    const float* Wl1 = (const float*)d_in[19]; const float* bl1 = (const float*)d_in[20];
    const float* Wl2 = (const float*)d_in[21]; const float* bl2 = (const float*)d_in[22];
    const float* Wl3 = (const float*)d_in[23]; const float* bl3 = (const float*)d_in[24];

    void* p;
    cudaGetSymbolAddress(&p, g_h0);        float* h0   = (float*)p;
    cudaGetSymbolAddress(&p, g_h1);        float* h1   = (float*)p;
    cudaGetSymbolAddress(&p, g_h2);        float* h2   = (float*)p;
    cudaGetSymbolAddress(&p, g_xw);        float* xw   = (float*)p;
    cudaGetSymbolAddress(&p, g_dis);       float* dis  = (float*)p;
    cudaGetSymbolAddress(&p, g_degI);      int* degI   = (int*)p;
    cudaGetSymbolAddress(&p, g_rowstart);  int* rowst  = (int*)p;
    cudaGetSymbolAddress(&p, g_cursor);    int* cursor = (int*)p;
    cudaGetSymbolAddress(&p, g_ecol);      int* ecol   = (int*)p;
    cudaGetSymbolAddress(&p, g_ctr);       int* ctr    = (int*)p;
    cudaGetSymbolAddress(&p, g_map);       int* map    = (int*)p;
    cudaGetSymbolAddress(&p, g_pool);      float* pool = (float*)p;
    cudaGetSymbolAddress(&p, g_degPI);     int* degPI  = (int*)p;
    cudaGetSymbolAddress(&p, g_rowstartP); int* rowstP = (int*)p;
    cudaGetSymbolAddress(&p, g_cursorP);   int* cursP  = (int*)p;
    cudaGetSymbolAddress(&p, g_ecolP);     int* ecolP  = (int*)p;
    cudaGetSymbolAddress(&p, g_disP);      float* disP = (float*)p;
    cudaGetSymbolAddress(&p, g_xwP);       float* xwP  = (float*)p;
    cudaGetSymbolAddress(&p, g_hP);        float* hP   = (float*)p;

    static bool attr_done = false;
    if (!attr_done) {
        cudaFuncSetAttribute(gemm_tf32, cudaFuncAttributeMaxDynamicSharedMemorySize, GEMM_SMEM);
        attr_done = true;
    }

    // launches 1-3, then #4 = the big tf32 GEMM (ncu window lands on the 4th launch)
    zero_all_kernel<<<256, 256>>>();                                       // 1
    degi_kernel<<<E_ALL / 256, 256>>>(dst_all, degI, E_ALL);               // 2
    assign_kernel<<<NTOT / 256, 256>>>(degI, rowst, cursor, dis, NTOT, ctr); // 3
    gemm_tf32<<<NTOT / 128, 256, GEMM_SMEM>>>(x, W1, xw, 128);             // 4  <-- profiled

    place_kernel<<<E_ALL / 256, 256>>>(src_all, dst_all, cursor, ecol, E_ALL);

    // ---- 3 GCN layers ----
    agg_kernel<<<NTOT / 8, 256>>>(xw, rowst, degI, ecol, dis, b1, h0, NTOT);
    gemm_tf32<<<NTOT / 128, 256, GEMM_SMEM>>>(h0, W2, xw, 128);
    agg_kernel<<<NTOT / 8, 256>>>(xw, rowst, degI, ecol, dis, b2, h1, NTOT);
    gemm_tf32<<<NTOT / 128, 256, GEMM_SMEM>>>(h1, W3, xw, 128);
    agg_kernel<<<NTOT / 8, 256>>>(xw, rowst, degI, ecol, dis, b3, h2, NTOT);

    // ---- dual attention pooling ----
    mean384_kernel<<<512, 384>>>();
    catt_kernel<<<128, 384>>>(Wg_att);
    alphagp_kernel<<<1024, 256>>>();
    pv_kernel<<<64, 768>>>(Wal, bal);
    pvnorm_kernel<<<128, 128>>>();

    // ---- CAG pool ----
    score_kernel<<<NTOT / 8, 256>>>();
    topk_kernel<<<128, 512>>>();
    gather_kernel<<<(2 * NPOOL) / 8, 256>>>();

    // ---- pooled CSR (combined over both clusters, scan-free) ----
    degPI_kernel<<<E_C / 256, 256>>>(src_c[0], dst_c[0], map, degPI, E_C);
    degPI_kernel<<<E_C / 256, 256>>>(src_c[1], dst_c[1], map + B_ * N1_, degPI + NPOOL, E_C);
    assign_kernel<<<(2 * NPOOL) / 256, 256>>>(degPI, rowstP, cursP, disP, 2 * NPOOL, ctr + 1);
    placeP_kernel<<<E_C / 256, 256>>>(src_c[0], dst_c[0], map, cursP, ecolP, E_C, 0);
    placeP_kernel<<<E_C / 256, 256>>>(src_c[1], dst_c[1], map + B_ * N1_, cursP, ecolP, E_C, NPOOL);

    // ---- pooled GCN (both clusters in one GEMM + one agg) ----
    gemm_tf32<<<(2 * NPOOL) / 128, 256, GEMM_SMEM>>>(pool, Wf, xwP, 384);
    agg_kernel<<<(2 * NPOOL) / 8, 256>>>(xwP, rowstP, degPI, ecolP, disP, bf, hP, 2 * NPOOL);

    // ---- final attention pools + MLP head ----
    meanF_kernel<<<256, 128>>>();
    cF_kernel<<<128, 128>>>(Wg_fin);
    alphaP_kernel<<<(2 * NPOOL) / 8, 256>>>();
    gfin_kernel<<<256, 128>>>();
    mlp_kernel<<<64, 128>>>(Wl1, bl1, Wl2, bl2, Wl3, bl3, (float*)d_out);
}

// round 10
// speedup vs baseline: 1.1041x; 1.1041x over previous
#include <cuda_runtime.h>
#include <math.h>
#include <stdint.h>

// Problem constants
#define B_      64
#define N1_     512
#define N2_     512
#define NPER    1024
#define NTOT    65536
#define KSEL    256
#define NPOOL   16384
#define E_ALL   1048576
#define E_C     524288

// ---------------- scratch ----------------
__device__ float g_h0[(size_t)NTOT * 128];
__device__ float g_h1[(size_t)NTOT * 128];
__device__ float g_h2[(size_t)NTOT * 128];
__device__ float g_xw[(size_t)NTOT * 128];
__device__ float g_dis[NTOT];

// CSR for the big graph
__device__ int g_degI[NTOT];
__device__ int g_rowstart[NTOT];
__device__ int g_cursor[NTOT];
__device__ int g_ecol[E_ALL];
__device__ int g_ctr[2];

__device__ float g_mean[128 * 384];
__device__ float g_catt[128 * 384];
__device__ float g_gp[128 * 384];
__device__ float g_pv[64 * 768];
__device__ float g_pvnorm[128];

__device__ float g_score[2][B_ * N1_];
__device__ int   g_map[2][B_ * N1_];
__device__ int   g_perm[2][B_ * KSEL];
__device__ float g_pool[2][(size_t)NPOOL * 384];

// pooled CSR (combined over both clusters)
__device__ int   g_degPI[2 * NPOOL];
__device__ int   g_rowstartP[2 * NPOOL];
__device__ int   g_cursorP[2 * NPOOL];
__device__ int   g_ecolP[2 * E_C];
__device__ float g_disP[2 * NPOOL];

__device__ float g_xwP[(size_t)2 * NPOOL * 128];
__device__ float g_hP[2][(size_t)NPOOL * 128];

__device__ float g_meanF[2][B_ * 128];
__device__ float g_cF[2][B_ * 128];
__device__ float g_alphaP[2][NPOOL];
__device__ float g_gfin[2][B_ * 128];

__device__ __forceinline__ float xcat_at(int node, int f) {
    const float* H = (f < 128) ? g_h0 : ((f < 256) ? g_h1 : g_h2);
    return H[(size_t)node * 128 + (f & 127)];
}
__device__ __forceinline__ float sigmoidf_(float x) { return 1.f / (1.f + expf(-x)); }

// ---------------- zero everything that accumulates ----------------
__global__ void zero_all_kernel() {
    const int NM = 128 * 384;
    int stride = gridDim.x * blockDim.x;
    for (int i = blockIdx.x * blockDim.x + threadIdx.x;
         i < NTOT + 2 * NPOOL + 2 + 2 * NM + 2 * 2 * B_ * 128; i += stride) {
        int j = i;
        if (j < NTOT) { g_degI[j] = 0; continue; }
        j -= NTOT;
        if (j < 2 * NPOOL) { g_degPI[j] = 0; continue; }
        j -= 2 * NPOOL;
        if (j < 2) { g_ctr[j] = 0; continue; }
        j -= 2;
        if (j < NM) { g_mean[j] = 0.f; continue; }
        j -= NM;
        if (j < NM) { g_gp[j] = 0.f; continue; }
        j -= NM;
        if (j < 2 * B_ * 128) { ((float*)g_meanF)[j] = 0.f; continue; }
        j -= 2 * B_ * 128;
        ((float*)g_gfin)[j] = 0.f;
    }
}

__global__ void degi_kernel(const int* __restrict__ dst, int* __restrict__ deg, int E) {
    int e = blockIdx.x * blockDim.x + threadIdx.x;
    if (e < E) atomicAdd(&deg[dst[e]], 1);
}
__global__ void degPI_kernel(const int* __restrict__ src, const int* __restrict__ dst,
                             const int* __restrict__ map, int* __restrict__ deg, int E) {
    int e = blockIdx.x * blockDim.x + threadIdx.x;
    if (e >= E) return;
    int r = map[src[e]], c = map[dst[e]];
    if (r >= 0 && c >= 0) atomicAdd(&deg[c], 1);
}

// rowstart assignment without scans: order-free atomic range grab.
__global__ void assign_kernel(const int* __restrict__ deg, int* __restrict__ rowstart,
                              int* __restrict__ cursor, float* __restrict__ dis,
                              int n, int* __restrict__ ctr) {
    int i = blockIdx.x * blockDim.x + threadIdx.x;
    if (i >= n) return;
    int d = deg[i];
    int rs = atomicAdd(ctr, d);
    rowstart[i] = rs;
    cursor[i] = rs;
    dis[i] = rsqrtf((float)d + 1.f);
}

// ---------------- CSR edge placement (cursor pre-seeded with rowstart) ----------------
__global__ void place_kernel(const int* __restrict__ src, const int* __restrict__ dst,
                             int* __restrict__ cursor, int* __restrict__ ecol, int E) {
    int e = blockIdx.x * blockDim.x + threadIdx.x;
    if (e >= E) return;
    int pos = atomicAdd(&cursor[dst[e]], 1);
    ecol[pos] = src[e];
}
__global__ void placeP_kernel(const int* __restrict__ src, const int* __restrict__ dst,
                              const int* __restrict__ map,
                              int* __restrict__ cursor, int* __restrict__ ecol, int E, int off) {
    int e = blockIdx.x * blockDim.x + threadIdx.x;
    if (e >= E) return;
    int r = map[src[e]], c = map[dst[e]];
    if (r < 0 || c < 0) return;
    int pos = atomicAdd(&cursor[c + off], 1);
    ecol[pos] = r + off;
}

// ============ 3xTF32 tensor-core GEMM (R8 configuration: separate hi/lo planes) ============
__device__ __forceinline__ uint32_t f2tf32(float x) {
    uint32_t y;
    asm("cvt.rna.tf32.f32 %0, %1;" : "=r"(y) : "f"(x));
    return y;
}
__device__ __forceinline__ void mma_tf32(float* c, const uint32_t* a, uint32_t b0, uint32_t b1) {
    asm volatile("mma.sync.aligned.m16n8k8.row.col.f32.tf32.tf32.f32 "
                 "{%0,%1,%2,%3}, {%4,%5,%6,%7}, {%8,%9}, {%0,%1,%2,%3};"
                 : "+f"(c[0]), "+f"(c[1]), "+f"(c[2]), "+f"(c[3])
                 : "r"(a[0]), "r"(a[1]), "r"(a[2]), "r"(a[3]), "r"(b0), "r"(b1));
}

#define AS_STRIDE 36
#define BS_STRIDE 136
#define GEMM_SMEM ((2 * 128 * AS_STRIDE + 2 * 32 * BS_STRIDE) * 4)  // 71680 B

__device__ __forceinline__ void ldg_chunk(const float* __restrict__ A, const float* __restrict__ W,
                                          int K, int R0, int k0, int tid,
                                          float4* ra, float4* rb) {
#pragma unroll
    for (int i = 0; i < 4; i++) {
        int q = tid + i * 256;
        int r = q >> 3, c4 = (q & 7) << 2;
        ra[i] = *(const float4*)(A + (size_t)(R0 + r) * K + k0 + c4);
    }
#pragma unroll
    for (int i = 0; i < 4; i++) {
        int q = tid + i * 256;
        int r = q >> 5, c4 = (q & 31) << 2;
        rb[i] = *(const float4*)(W + (size_t)(k0 + r) * 128 + c4);
    }
}

__device__ __forceinline__ void split_store(float* hiP, float* loP, float v) {
    float h = __uint_as_float(f2tf32(v));
    *hiP = h;
    *loP = __uint_as_float(f2tf32(v - h));
}

__device__ __forceinline__ void sts_chunk(float* AsH, float* AsL, float* BsH, float* BsL,
                                          int tid, const float4* ra, const float4* rb) {
#pragma unroll
    for (int i = 0; i < 4; i++) {
        int q = tid + i * 256;
        int r = q >> 3, c4 = (q & 7) << 2;
        int o = r * AS_STRIDE + c4;
        split_store(AsH + o + 0, AsL + o + 0, ra[i].x);
        split_store(AsH + o + 1, AsL + o + 1, ra[i].y);
        split_store(AsH + o + 2, AsL + o + 2, ra[i].z);
        split_store(AsH + o + 3, AsL + o + 3, ra[i].w);
    }
#pragma unroll
    for (int i = 0; i < 4; i++) {
        int q = tid + i * 256;
        int r = q >> 5, c4 = (q & 31) << 2;
        int o = r * BS_STRIDE + c4;
        split_store(BsH + o + 0, BsL + o + 0, rb[i].x);
        split_store(BsH + o + 1, BsL + o + 1, rb[i].y);
        split_store(BsH + o + 2, BsL + o + 2, rb[i].z);
        split_store(BsH + o + 3, BsL + o + 3, rb[i].w);
    }
}

__global__ void __launch_bounds__(256, 2) gemm_tf32(
    const float* __restrict__ A, const float* __restrict__ W,
    float* __restrict__ C, int K)
{
    extern __shared__ float sm[];
    float* AsH = sm;
    float* AsL = AsH + 128 * AS_STRIDE;
    float* BsH = AsL + 128 * AS_STRIDE;
    float* BsL = BsH + 32 * BS_STRIDE;

    int tid = threadIdx.x, lane = tid & 31, w = tid >> 5;
    int mw = w >> 1, nw = w & 1;
    int R0 = blockIdx.x * 128;

    float c[2][8][4];
#pragma unroll
    for (int mi = 0; mi < 2; mi++)
#pragma unroll
        for (int ni = 0; ni < 8; ni++)
#pragma unroll
            for (int k = 0; k < 4; k++) c[mi][ni][k] = 0.f;

    float4 ra[4], rb[4];
    ldg_chunk(A, W, K, R0, 0, tid, ra, rb);
    sts_chunk(AsH, AsL, BsH, BsL, tid, ra, rb);

    int nch = K >> 5;
    for (int ch = 0; ch < nch; ch++) {
        __syncthreads();
        if (ch + 1 < nch) ldg_chunk(A, W, K, R0, (ch + 1) << 5, tid, ra, rb);
#pragma unroll
        for (int step = 0; step < 4; step++) {
            int kk = step * 8;
            uint32_t aH[2][4], aL[2][4];
#pragma unroll
            for (int mi = 0; mi < 2; mi++) {
                int r = mw * 32 + mi * 16 + (lane >> 2);
                int cc = kk + (lane & 3);
                int o0 = r * AS_STRIDE + cc, o1 = (r + 8) * AS_STRIDE + cc;
                aH[mi][0] = __float_as_uint(AsH[o0]);
                aH[mi][1] = __float_as_uint(AsH[o1]);
                aH[mi][2] = __float_as_uint(AsH[o0 + 4]);
                aH[mi][3] = __float_as_uint(AsH[o1 + 4]);
                aL[mi][0] = __float_as_uint(AsL[o0]);
                aL[mi][1] = __float_as_uint(AsL[o1]);
                aL[mi][2] = __float_as_uint(AsL[o0 + 4]);
                aL[mi][3] = __float_as_uint(AsL[o1 + 4]);
            }
#pragma unroll
            for (int ni = 0; ni < 8; ni++) {
                int n = nw * 64 + ni * 8 + (lane >> 2);
                int ob0 = (kk + (lane & 3)) * BS_STRIDE + n;
                int ob1 = (kk + 4 + (lane & 3)) * BS_STRIDE + n;
                uint32_t bH0 = __float_as_uint(BsH[ob0]);
                uint32_t bH1 = __float_as_uint(BsH[ob1]);
                uint32_t bL0 = __float_as_uint(BsL[ob0]);
                uint32_t bL1 = __float_as_uint(BsL[ob1]);
                mma_tf32(c[0][ni], aL[0], bH0, bH1);
                mma_tf32(c[1][ni], aL[1], bH0, bH1);
                mma_tf32(c[0][ni], aH[0], bL0, bL1);
                mma_tf32(c[1][ni], aH[1], bL0, bL1);
                mma_tf32(c[0][ni], aH[0], bH0, bH1);
                mma_tf32(c[1][ni], aH[1], bH0, bH1);
            }
        }
        if (ch + 1 < nch) {
            __syncthreads();
            sts_chunk(AsH, AsL, BsH, BsL, tid, ra, rb);
        }
    }

#pragma unroll
    for (int mi = 0; mi < 2; mi++) {
#pragma unroll
        for (int ni = 0; ni < 8; ni++) {
            int row = R0 + mw * 32 + mi * 16 + (lane >> 2);
            int col = nw * 64 + ni * 8 + 2 * (lane & 3);
            *(float2*)(C + (size_t)row * 128 + col) = make_float2(c[mi][ni][0], c[mi][ni][1]);
            *(float2*)(C + (size_t)(row + 8) * 128 + col) = make_float2(c[mi][ni][2], c[mi][ni][3]);
        }
    }
}

// ---------------- CSR gather-aggregate + self loop + bias + relu (4-way unrolled) ----------------
__global__ void __launch_bounds__(256) agg_kernel(
    const float* __restrict__ xw,
    const int* __restrict__ rowstart, const int* __restrict__ degI,
    const int* __restrict__ ecol, const float* __restrict__ dis,
    const float* __restrict__ bias, float* __restrict__ out, int n)
{
    int w = (blockIdx.x * blockDim.x + threadIdx.x) >> 5;
    if (w >= n) return;
    int lane = threadIdx.x & 31;
    int rs = rowstart[w];
    int re = rs + degI[w];
    float4 a0 = make_float4(0.f, 0.f, 0.f, 0.f);
    float4 a1 = make_float4(0.f, 0.f, 0.f, 0.f);
    float4 a2 = make_float4(0.f, 0.f, 0.f, 0.f);
    float4 a3 = make_float4(0.f, 0.f, 0.f, 0.f);
    int i = rs;
    for (; i + 4 <= re; i += 4) {
        int s0 = ecol[i], s1 = ecol[i + 1], s2 = ecol[i + 2], s3 = ecol[i + 3];
        float w0 = dis[s0], w1 = dis[s1], w2 = dis[s2], w3 = dis[s3];
        float4 v0 = *(const float4*)(xw + (size_t)s0 * 128 + lane * 4);
        float4 v1 = *(const float4*)(xw + (size_t)s1 * 128 + lane * 4);
        float4 v2 = *(const float4*)(xw + (size_t)s2 * 128 + lane * 4);
        float4 v3 = *(const float4*)(xw + (size_t)s3 * 128 + lane * 4);
        a0.x = fmaf(v0.x, w0, a0.x); a0.y = fmaf(v0.y, w0, a0.y);
        a0.z = fmaf(v0.z, w0, a0.z); a0.w = fmaf(v0.w, w0, a0.w);
        a1.x = fmaf(v1.x, w1, a1.x); a1.y = fmaf(v1.y, w1, a1.y);
        a1.z = fmaf(v1.z, w1, a1.z); a1.w = fmaf(v1.w, w1, a1.w);
        a2.x = fmaf(v2.x, w2, a2.x); a2.y = fmaf(v2.y, w2, a2.y);
        a2.z = fmaf(v2.z, w2, a2.z); a2.w = fmaf(v2.w, w2, a2.w);
        a3.x = fmaf(v3.x, w3, a3.x); a3.y = fmaf(v3.y, w3, a3.y);
        a3.z = fmaf(v3.z, w3, a3.z); a3.w = fmaf(v3.w, w3, a3.w);
    }
    for (; i < re; i++) {
        int s0 = ecol[i];
        float w0 = dis[s0];
        float4 v0 = *(const float4*)(xw + (size_t)s0 * 128 + lane * 4);
        a0.x = fmaf(v0.x, w0, a0.x); a0.y = fmaf(v0.y, w0, a0.y);
        a0.z = fmaf(v0.z, w0, a0.z); a0.w = fmaf(v0.w, w0, a0.w);
    }
    a0.x += a1.x + a2.x + a3.x;
    a0.y += a1.y + a2.y + a3.y;
    a0.z += a1.z + a2.z + a3.z;
    a0.w += a1.w + a2.w + a3.w;
    float dd = dis[w];
    float sw = dd * dd;
    float4 self = *(const float4*)(xw + (size_t)w * 128 + lane * 4);
    float4 r;
    r.x = fmaxf(fmaf(a0.x, dd, fmaf(self.x, sw, bias[lane * 4 + 0])), 0.f);
    r.y = fmaxf(fmaf(a0.y, dd, fmaf(self.y, sw, bias[lane * 4 + 1])), 0.f);
    r.z = fmaxf(fmaf(a0.z, dd, fmaf(self.z, sw, bias[lane * 4 + 2])), 0.f);
    r.w = fmaxf(fmaf(a0.w, dd, fmaf(self.w, sw, bias[lane * 4 + 3])), 0.f);
    *(float4*)(out + (size_t)w * 128 + lane * 4) = r;
}

// ---------------- attention pool (big, 384 feats) ----------------
__global__ void mean384_kernel() {
    int s = blockIdx.x >> 2, ch = blockIdx.x & 3;
    int f = threadIdx.x;
    int g = s & 63, cl = s >> 6;
    int base = g * NPER + cl * N1_ + ch * 128;
    float acc = 0.f;
#pragma unroll 4
    for (int j = 0; j < 128; j++) acc += xcat_at(base + j, f);
    atomicAdd(&g_mean[s * 384 + f], acc);
}

__global__ void catt_kernel(const float* __restrict__ Wg) {
    __shared__ float m[384];
    int s = blockIdx.x, f = threadIdx.x;
    m[f] = g_mean[s * 384 + f] * (1.f / 512.f);
    __syncthreads();
    float acc = 0.f;
    for (int k = 0; k < 384; k++) acc = fmaf(m[k], Wg[k * 384 + f], acc);
    g_catt[s * 384 + f] = tanhf(acc);
}

// fused alpha + gp: one xcat pass.
__global__ void __launch_bounds__(256) alphagp_kernel() {
    int blk = blockIdx.x;
    int s = blk >> 3, ch = blk & 7;
    int g = s & 63, cl = s >> 6;
    int base = g * NPER + cl * N1_ + ch * 64;
    int wid = threadIdx.x >> 5, lane = threadIdx.x & 31;
    __shared__ float csh[384];
    __shared__ float gpsh[384];
    for (int t = threadIdx.x; t < 384; t += 256) { csh[t] = g_catt[s * 384 + t]; gpsh[t] = 0.f; }
    __syncthreads();
    float acc[12];
#pragma unroll
    for (int q = 0; q < 12; q++) acc[q] = 0.f;
    for (int j = 0; j < 8; j++) {
        int node = base + wid * 8 + j;
        float xv[12];
        float dot = 0.f;
#pragma unroll
        for (int q = 0; q < 12; q++) {
            int f = q * 32 + lane;
            xv[q] = xcat_at(node, f);
            dot = fmaf(xv[q], csh[f], dot);
        }
#pragma unroll
        for (int o = 16; o; o >>= 1) dot += __shfl_xor_sync(0xffffffffu, dot, o);
        float alpha = sigmoidf_(dot);
#pragma unroll
        for (int q = 0; q < 12; q++) acc[q] = fmaf(xv[q], alpha, acc[q]);
    }
#pragma unroll
    for (int q = 0; q < 12; q++) atomicAdd(&gpsh[q * 32 + lane], acc[q]);
    __syncthreads();
    for (int t = threadIdx.x; t < 384; t += 256) atomicAdd(&g_gp[s * 384 + t], gpsh[t]);
}

__global__ void pv_kernel(const float* __restrict__ Wal, const float* __restrict__ bal) {
    __shared__ float in[768];
    int g = blockIdx.x, t = threadIdx.x;
    in[t] = (t < 384) ? g_gp[g * 384 + t] : g_gp[(64 + g) * 384 + (t - 384)];
    __syncthreads();
    float acc = bal[t];
    for (int k = 0; k < 768; k++) acc = fmaf(in[k], Wal[k * 768 + t], acc);
    g_pv[g * 768 + t] = acc;
}

__global__ void pvnorm_kernel() {
    int b = blockIdx.x;
    int cl = b >> 6, g = b & 63;
    int t = threadIdx.x;
    float acc = 0.f;
    for (int k = t; k < 384; k += 128) {
        float v = g_pv[g * 768 + cl * 384 + k];
        acc += v * v;
    }
    __shared__ float red[128];
    red[t] = acc;
    __syncthreads();
    for (int o = 64; o; o >>= 1) {
        if (t < o) red[t] += red[t + o];
        __syncthreads();
    }
    if (!t) g_pvnorm[b] = sqrtf(red[0]);
}

// ---------------- CAG pool ----------------
__global__ void score_kernel() {
    int w = (blockIdx.x * blockDim.x + threadIdx.x) >> 5;
    if (w >= NTOT) return;
    int lane = threadIdx.x & 31;
    int cl = w >> 15;
    int rem = w & 32767;
    int g = rem >> 9, j = rem & 511;
    int node = g * NPER + cl * N1_ + j;
    const float* q = g_pv + g * 768 + cl * 384;
    float acc = 0.f;
    for (int t = lane; t < 384; t += 32) acc += xcat_at(node, t) * q[t];
#pragma unroll
    for (int o = 16; o; o >>= 1) acc += __shfl_xor_sync(0xffffffffu, acc, o);
    if (!lane) g_score[cl][g * 512 + j] = acc / g_pvnorm[cl * 64 + g];
}

__global__ void topk_kernel() {
    int b = blockIdx.x;
    int cl = b >> 6, g = b & 63;
    int j = threadIdx.x;
    __shared__ float s[512];
    s[j] = g_score[cl][g * 512 + j];
    __syncthreads();
    float mys = s[j];
    int rank = 0;
    for (int i = 0; i < 512; i++) {
        float o = s[i];
        rank += (o > mys) || (o == mys && i < j);
    }
    g_map[cl][g * 512 + j] = (rank < KSEL) ? (g * KSEL + rank) : -1;
    if (rank < KSEL) g_perm[cl][g * KSEL + rank] = j;
}

__global__ void gather_kernel() {
    int w = (blockIdx.x * blockDim.x + threadIdx.x) >> 5;
    if (w >= 2 * NPOOL) return;
    int lane = threadIdx.x & 31;
    int cl = w >> 14;
    int r = w & (NPOOL - 1);
    int g = r >> 8;
    int j = g_perm[cl][r];
    int node = g * NPER + cl * N1_ + j;
    float gate = sigmoidf_(g_score[cl][g * 512 + j]);
    float* o = g_pool[cl] + (size_t)r * 384;
    for (int t = lane; t < 384; t += 32) o[t] = xcat_at(node, t) * gate;
}

// ---------------- final attention pool ----------------
__global__ void meanF_kernel() {
    int b = blockIdx.x >> 1, ch = blockIdx.x & 1;
    int cl = b >> 6, g = b & 63;
    int f = threadIdx.x;
    const float* h = g_hP[cl] + ((size_t)g * KSEL + ch * 128) * 128;
    float acc = 0.f;
#pragma unroll 4
    for (int j = 0; j < 128; j++) acc += h[(size_t)j * 128 + f];
    atomicAdd(&g_meanF[cl][g * 128 + f], acc);
}

__global__ void cF_kernel(const float* __restrict__ Wg) {
    int b = blockIdx.x;
    int cl = b >> 6, g = b & 63;
    int f = threadIdx.x;
    __shared__ float m[128];
    m[f] = g_meanF[cl][g * 128 + f] * (1.f / 256.f);
    __syncthreads();
    float acc = 0.f;
    for (int k = 0; k < 128; k++) acc = fmaf(m[k], Wg[k * 128 + f], acc);
    g_cF[cl][g * 128 + f] = tanhf(acc);
}

__global__ void alphaP_kernel() {
    int w = (blockIdx.x * blockDim.x + threadIdx.x) >> 5;
    if (w >= 2 * NPOOL) return;
    int lane = threadIdx.x & 31;
    int cl = w >> 14;
    int r = w & (NPOOL - 1);
    int g = r >> 8;
    const float* h = g_hP[cl] + (size_t)r * 128;
    const float* c = g_cF[cl] + g * 128;
    float acc = 0.f;
    for (int t = lane; t < 128; t += 32) acc += h[t] * c[t];
#pragma unroll
    for (int o = 16; o; o >>= 1) acc += __shfl_xor_sync(0xffffffffu, acc, o);
    if (!lane) g_alphaP[cl][r] = sigmoidf_(acc);
}

__global__ void gfin_kernel() {
    int b = blockIdx.x >> 1, ch = blockIdx.x & 1;
    int cl = b >> 6, g = b & 63;
    int f = threadIdx.x;
    float acc = 0.f;
#pragma unroll 4
    for (int j = 0; j < 128; j++) {
        int r = g * KSEL + ch * 128 + j;
        acc = fmaf(g_hP[cl][(size_t)r * 128 + f], g_alphaP[cl][r], acc);
    }
    atomicAdd(&g_gfin[cl][g * 128 + f], acc);
}

// ---------------- final MLP ----------------
__global__ void mlp_kernel(const float* __restrict__ Wl1, const float* __restrict__ bl1,
                           const float* __restrict__ Wl2, const float* __restrict__ bl2,
                           const float* __restrict__ Wl3, const float* __restrict__ bl3,
                           float* __restrict__ out)
{
    __shared__ float in[256];
    __shared__ float z1[128];
    __shared__ float z2[64];
    int g = blockIdx.x, t = threadIdx.x;
    in[t] = g_gfin[0][g * 128 + t];
    in[128 + t] = g_gfin[1][g * 128 + t];
    __syncthreads();
    float a = bl1[t];
    for (int k = 0; k < 256; k++) a = fmaf(in[k], Wl1[k * 128 + t], a);
    z1[t] = fmaxf(a, 0.f);
    __syncthreads();
    if (t < 64) {
        float a2 = bl2[t];
        for (int k = 0; k < 128; k++) a2 = fmaf(z1[k], Wl2[k * 64 + t], a2);
        z2[t] = fmaxf(a2, 0.f);
    }
    __syncthreads();
    if (t < 2) {
        float a3 = bl3[t];
        for (int k = 0; k < 64; k++) a3 = fmaf(z2[k], Wl3[k * 2 + t], a3);
        out[g * 2 + t] = a3;
    }
}

// ---------------- host orchestration ----------------
extern "C" void kernel_launch(void* const* d_in, const int* in_sizes, int n_in,
                              void* d_out, int out_size)
{
    const float* x       = (const float*)d_in[0];
    const int*   src_all = (const int*)d_in[1];
    const int*   dst_all = (const int*)d_in[2];
    const int*   src_c[2] = { (const int*)d_in[3], (const int*)d_in[5] };
    const int*   dst_c[2] = { (const int*)d_in[4], (const int*)d_in[6] };
    const float* W1 = (const float*)d_in[7];  const float* b1 = (const float*)d_in[8];
    const float* W2 = (const float*)d_in[9];  const float* b2 = (const float*)d_in[10];
    const float* W3 = (const float*)d_in[11]; const float* b3 = (const float*)d_in[12];
    const float* Wg_att = (const float*)d_in[13];
    const float* Wal = (const float*)d_in[14]; const float* bal = (const float*)d_in[15];
    const float* Wf  = (const float*)d_in[16]; const float* bf  = (const float*)d_in[17];
    const float* Wg_fin = (const float*)d_in[18];
    const float* Wl1 = (const float*)d_in[19]; const float* bl1 = (const float*)d_in[20];
    const float* Wl2 = (const float*)d_in[21]; const float* bl2 = (const float*)d_in[22];
    const float* Wl3 = (const float*)d_in[23]; const float* bl3 = (const float*)d_in[24];

    void* p;
    cudaGetSymbolAddress(&p, g_h0);        float* h0   = (float*)p;
    cudaGetSymbolAddress(&p, g_h1);        float* h1   = (float*)p;
    cudaGetSymbolAddress(&p, g_h2);        float* h2   = (float*)p;
    cudaGetSymbolAddress(&p, g_xw);        float* xw   = (float*)p;
    cudaGetSymbolAddress(&p, g_dis);       float* dis  = (float*)p;
    cudaGetSymbolAddress(&p, g_degI);      int* degI   = (int*)p;
    cudaGetSymbolAddress(&p, g_rowstart);  int* rowst  = (int*)p;
    cudaGetSymbolAddress(&p, g_cursor);    int* cursor = (int*)p;
    cudaGetSymbolAddress(&p, g_ecol);      int* ecol   = (int*)p;
    cudaGetSymbolAddress(&p, g_ctr);       int* ctr    = (int*)p;
    cudaGetSymbolAddress(&p, g_map);       int* map    = (int*)p;
    cudaGetSymbolAddress(&p, g_pool);      float* pool = (float*)p;
    cudaGetSymbolAddress(&p, g_degPI);     int* degPI  = (int*)p;
    cudaGetSymbolAddress(&p, g_rowstartP); int* rowstP = (int*)p;
    cudaGetSymbolAddress(&p, g_cursorP);   int* cursP  = (int*)p;
    cudaGetSymbolAddress(&p, g_ecolP);     int* ecolP  = (int*)p;
    cudaGetSymbolAddress(&p, g_disP);      float* disP = (float*)p;
    cudaGetSymbolAddress(&p, g_xwP);       float* xwP  = (float*)p;
    cudaGetSymbolAddress(&p, g_hP);        float* hP   = (float*)p;

    static bool attr_done = false;
    if (!attr_done) {
        cudaFuncSetAttribute(gemm_tf32, cudaFuncAttributeMaxDynamicSharedMemorySize, GEMM_SMEM);
        attr_done = true;
    }

    // launches 1-3, then #4 = the big tf32 GEMM (ncu window lands on the 4th launch)
    zero_all_kernel<<<256, 256>>>();                                         // 1
    degi_kernel<<<E_ALL / 256, 256>>>(dst_all, degI, E_ALL);                 // 2
    assign_kernel<<<NTOT / 256, 256>>>(degI, rowst, cursor, dis, NTOT, ctr); // 3
    gemm_tf32<<<NTOT / 128, 256, GEMM_SMEM>>>(x, W1, xw, 128);               // 4  <-- profiled

    place_kernel<<<E_ALL / 256, 256>>>(src_all, dst_all, cursor, ecol, E_ALL);

    // ---- 3 GCN layers ----
    agg_kernel<<<NTOT / 8, 256>>>(xw, rowst, degI, ecol, dis, b1, h0, NTOT);
    gemm_tf32<<<NTOT / 128, 256, GEMM_SMEM>>>(h0, W2, xw, 128);
    agg_kernel<<<NTOT / 8, 256>>>(xw, rowst, degI, ecol, dis, b2, h1, NTOT);
    gemm_tf32<<<NTOT / 128, 256, GEMM_SMEM>>>(h1, W3, xw, 128);
    agg_kernel<<<NTOT / 8, 256>>>(xw, rowst, degI, ecol, dis, b3, h2, NTOT);

    // ---- dual attention pooling ----
    mean384_kernel<<<512, 384>>>();
    catt_kernel<<<128, 384>>>(Wg_att);
    alphagp_kernel<<<1024, 256>>>();
    pv_kernel<<<64, 768>>>(Wal, bal);
    pvnorm_kernel<<<128, 128>>>();

    // ---- CAG pool ----
    score_kernel<<<NTOT / 8, 256>>>();
    topk_kernel<<<128, 512>>>();
    gather_kernel<<<(2 * NPOOL) / 8, 256>>>();

    // ---- pooled CSR (combined over both clusters, scan-free) ----
    degPI_kernel<<<E_C / 256, 256>>>(src_c[0], dst_c[0], map, degPI, E_C);
    degPI_kernel<<<E_C / 256, 256>>>(src_c[1], dst_c[1], map + B_ * N1_, degPI + NPOOL, E_C);
    assign_kernel<<<(2 * NPOOL) / 256, 256>>>(degPI, rowstP, cursP, disP, 2 * NPOOL, ctr + 1);
    placeP_kernel<<<E_C / 256, 256>>>(src_c[0], dst_c[0], map, cursP, ecolP, E_C, 0);
    placeP_kernel<<<E_C / 256, 256>>>(src_c[1], dst_c[1], map + B_ * N1_, cursP, ecolP, E_C, NPOOL);

    // ---- pooled GCN (both clusters in one GEMM + one agg) ----
    gemm_tf32<<<(2 * NPOOL) / 128, 256, GEMM_SMEM>>>(pool, Wf, xwP, 384);
    agg_kernel<<<(2 * NPOOL) / 8, 256>>>(xwP, rowstP, degPI, ecolP, disP, bf, hP, 2 * NPOOL);

    // ---- final attention pools + MLP head ----
    meanF_kernel<<<256, 128>>>();
    cF_kernel<<<128, 128>>>(Wg_fin);
    alphaP_kernel<<<(2 * NPOOL) / 8, 256>>>();
    gfin_kernel<<<256, 128>>>();
    mlp_kernel<<<64, 128>>>(Wl1, bl1, Wl2, bl2, Wl3, bl3, (float*)d_out);
}

// round 13
// speedup vs baseline: 1.1154x; 1.0102x over previous
#include <cuda_runtime.h>
#include <math.h>
#include <stdint.h>

// Problem constants
#define B_      64
#define N1_     512
#define N2_     512
#define NPER    1024
#define NTOT    65536
#define KSEL    256
#define NPOOL   16384
#define E_ALL   1048576
#define E_C     524288

// ---------------- scratch ----------------
__device__ float g_h0[(size_t)NTOT * 128];
__device__ float g_h1[(size_t)NTOT * 128];
__device__ float g_h2[(size_t)NTOT * 128];
__device__ float g_xw[(size_t)NTOT * 128];
__device__ float g_dis[NTOT];

// CSR for the big graph
__device__ int g_degI[NTOT];
__device__ int g_rowstart[NTOT];
__device__ int g_cursor[NTOT];
__device__ int g_ecol[E_ALL];
__device__ int g_ctr[2];

__device__ float g_mean[128 * 384];
__device__ float g_catt[128 * 384];
__device__ float g_gp[128 * 384];
__device__ float g_pv[64 * 768];
__device__ float g_pvnorm[128];

__device__ float g_score[2][B_ * N1_];
__device__ int   g_map[2][B_ * N1_];
__device__ int   g_perm[2][B_ * KSEL];
__device__ float g_pool[2][(size_t)NPOOL * 384];

// pooled CSR (combined over both clusters)
__device__ int   g_degPI[2 * NPOOL];
__device__ int   g_rowstartP[2 * NPOOL];
__device__ int   g_cursorP[2 * NPOOL];
__device__ int   g_ecolP[2 * E_C];
__device__ float g_disP[2 * NPOOL];

__device__ float g_xwP[(size_t)2 * NPOOL * 128];
__device__ float g_hP[2][(size_t)NPOOL * 128];

__device__ float g_meanF[2][B_ * 128];
__device__ float g_cF[2][B_ * 128];
__device__ float g_alphaP[2][NPOOL];
__device__ float g_gfin[2][B_ * 128];

__device__ __forceinline__ float xcat_at(int node, int f) {
    const float* H = (f < 128) ? g_h0 : ((f < 256) ? g_h1 : g_h2);
    return H[(size_t)node * 128 + (f & 127)];
}
__device__ __forceinline__ float sigmoidf_(float x) { return 1.f / (1.f + expf(-x)); }

// ---------------- zero everything that accumulates ----------------
__global__ void zero_all_kernel() {
    const int NM = 128 * 384;
    int stride = gridDim.x * blockDim.x;
    for (int i = blockIdx.x * blockDim.x + threadIdx.x;
         i < NTOT + 2 * NPOOL + 2 + 2 * NM + 2 * 2 * B_ * 128; i += stride) {
        int j = i;
        if (j < NTOT) { g_degI[j] = 0; continue; }
        j -= NTOT;
        if (j < 2 * NPOOL) { g_degPI[j] = 0; continue; }
        j -= 2 * NPOOL;
        if (j < 2) { g_ctr[j] = 0; continue; }
        j -= 2;
        if (j < NM) { g_mean[j] = 0.f; continue; }
        j -= NM;
        if (j < NM) { g_gp[j] = 0.f; continue; }
        j -= NM;
        if (j < 2 * B_ * 128) { ((float*)g_meanF)[j] = 0.f; continue; }
        j -= 2 * B_ * 128;
        ((float*)g_gfin)[j] = 0.f;
    }
}

__global__ void degi_kernel(const int* __restrict__ dst, int* __restrict__ deg, int E) {
    int e = blockIdx.x * blockDim.x + threadIdx.x;
    if (e < E) atomicAdd(&deg[dst[e]], 1);
}

// combined pooled degree count over both clusters
__global__ void degPI2_kernel(const int* __restrict__ src0, const int* __restrict__ dst0,
                              const int* __restrict__ src1, const int* __restrict__ dst1) {
    int e = blockIdx.x * blockDim.x + threadIdx.x;
    if (e < E_C) {
        int r = g_map[0][src0[e]], c = g_map[0][dst0[e]];
        if (r >= 0 && c >= 0) atomicAdd(&g_degPI[c], 1);
    } else {
        e -= E_C;
        int r = g_map[1][src1[e]], c = g_map[1][dst1[e]];
        if (r >= 0 && c >= 0) atomicAdd(&g_degPI[NPOOL + c], 1);
    }
}

// rowstart assignment without scans: order-free atomic range grab.
__global__ void assign_kernel(const int* __restrict__ deg, int* __restrict__ rowstart,
                              int* __restrict__ cursor, float* __restrict__ dis,
                              int n, int* __restrict__ ctr) {
    int i = blockIdx.x * blockDim.x + threadIdx.x;
    if (i >= n) return;
    int d = deg[i];
    int rs = atomicAdd(ctr, d);
    rowstart[i] = rs;
    cursor[i] = rs;
    dis[i] = rsqrtf((float)d + 1.f);
}

// ---------------- CSR edge placement (cursor pre-seeded with rowstart) ----------------
__global__ void place_kernel(const int* __restrict__ src, const int* __restrict__ dst,
                             int* __restrict__ cursor, int* __restrict__ ecol, int E) {
    int e = blockIdx.x * blockDim.x + threadIdx.x;
    if (e >= E) return;
    int pos = atomicAdd(&cursor[dst[e]], 1);
    ecol[pos] = src[e];
}
// combined pooled placement over both clusters
__global__ void placeP2_kernel(const int* __restrict__ src0, const int* __restrict__ dst0,
                               const int* __restrict__ src1, const int* __restrict__ dst1) {
    int e = blockIdx.x * blockDim.x + threadIdx.x;
    int cl = 0, off = 0;
    const int* S = src0;
    const int* D = dst0;
    if (e >= E_C) { e -= E_C; S = src1; D = dst1; cl = 1; off = NPOOL; }
    int r = g_map[cl][S[e]], c = g_map[cl][D[e]];
    if (r < 0 || c < 0) return;
    int pos = atomicAdd(&g_cursorP[c + off], 1);
    g_ecolP[pos] = r + off;
}

// ============ 3xTF32 tensor-core GEMM (separate hi/lo planes) ============
__device__ __forceinline__ uint32_t f2tf32(float x) {
    uint32_t y;
    asm("cvt.rna.tf32.f32 %0, %1;" : "=r"(y) : "f"(x));
    return y;
}
__device__ __forceinline__ void mma_tf32(float* c, const uint32_t* a, uint32_t b0, uint32_t b1) {
    asm volatile("mma.sync.aligned.m16n8k8.row.col.f32.tf32.tf32.f32 "
                 "{%0,%1,%2,%3}, {%4,%5,%6,%7}, {%8,%9}, {%0,%1,%2,%3};"
                 : "+f"(c[0]), "+f"(c[1]), "+f"(c[2]), "+f"(c[3])
                 : "r"(a[0]), "r"(a[1]), "r"(a[2]), "r"(a[3]), "r"(b0), "r"(b1));
}

#define AS_STRIDE 36
#define BS_STRIDE 136
#define GEMM_SMEM ((2 * 128 * AS_STRIDE + 2 * 32 * BS_STRIDE) * 4)  // 71680 B

__device__ __forceinline__ void ldg_chunk(const float* __restrict__ A, const float* __restrict__ W,
                                          int K, int R0, int k0, int tid,
                                          float4* ra, float4* rb) {
#pragma unroll
    for (int i = 0; i < 4; i++) {
        int q = tid + i * 256;
        int r = q >> 3, c4 = (q & 7) << 2;
        ra[i] = *(const float4*)(A + (size_t)(R0 + r) * K + k0 + c4);
    }
#pragma unroll
    for (int i = 0; i < 4; i++) {
        int q = tid + i * 256;
        int r = q >> 5, c4 = (q & 31) << 2;
        rb[i] = *(const float4*)(W + (size_t)(k0 + r) * 128 + c4);
    }
}

__device__ __forceinline__ void split_store(float* hiP, float* loP, float v) {
    float h = __uint_as_float(f2tf32(v));
    *hiP = h;
    *loP = __uint_as_float(f2tf32(v - h));
}

__device__ __forceinline__ void sts_chunk(float* AsH, float* AsL, float* BsH, float* BsL,
                                          int tid, const float4* ra, const float4* rb) {
#pragma unroll
    for (int i = 0; i < 4; i++) {
        int q = tid + i * 256;
        int r = q >> 3, c4 = (q & 7) << 2;
        int o = r * AS_STRIDE + c4;
        split_store(AsH + o + 0, AsL + o + 0, ra[i].x);
        split_store(AsH + o + 1, AsL + o + 1, ra[i].y);
        split_store(AsH + o + 2, AsL + o + 2, ra[i].z);
        split_store(AsH + o + 3, AsL + o + 3, ra[i].w);
    }
#pragma unroll
    for (int i = 0; i < 4; i++) {
        int q = tid + i * 256;
        int r = q >> 5, c4 = (q & 31) << 2;
        int o = r * BS_STRIDE + c4;
        split_store(BsH + o + 0, BsL + o + 0, rb[i].x);
        split_store(BsH + o + 1, BsL + o + 1, rb[i].y);
        split_store(BsH + o + 2, BsL + o + 2, rb[i].z);
        split_store(BsH + o + 3, BsL + o + 3, rb[i].w);
    }
}

__global__ void __launch_bounds__(256, 2) gemm_tf32(
    const float* __restrict__ A, const float* __restrict__ W,
    float* __restrict__ C, int K)
{
    extern __shared__ float sm[];
    float* AsH = sm;
    float* AsL = AsH + 128 * AS_STRIDE;
    float* BsH = AsL + 128 * AS_STRIDE;
    float* BsL = BsH + 32 * BS_STRIDE;

    int tid = threadIdx.x, lane = tid & 31, w = tid >> 5;
    int mw = w >> 1, nw = w & 1;
    int R0 = blockIdx.x * 128;

    float c[2][8][4];
#pragma unroll
    for (int mi = 0; mi < 2; mi++)
#pragma unroll
        for (int ni = 0; ni < 8; ni++)
#pragma unroll
            for (int k = 0; k < 4; k++) c[mi][ni][k] = 0.f;

    float4 ra[4], rb[4];
    ldg_chunk(A, W, K, R0, 0, tid, ra, rb);
    sts_chunk(AsH, AsL, BsH, BsL, tid, ra, rb);

    int nch = K >> 5;
    for (int ch = 0; ch < nch; ch++) {
        __syncthreads();
        if (ch + 1 < nch) ldg_chunk(A, W, K, R0, (ch + 1) << 5, tid, ra, rb);
#pragma unroll
        for (int step = 0; step < 4; step++) {
            int kk = step * 8;
            uint32_t aH[2][4], aL[2][4];
#pragma unroll
            for (int mi = 0; mi < 2; mi++) {
                int r = mw * 32 + mi * 16 + (lane >> 2);
                int cc = kk + (lane & 3);
                int o0 = r * AS_STRIDE + cc, o1 = (r + 8) * AS_STRIDE + cc;
                aH[mi][0] = __float_as_uint(AsH[o0]);
                aH[mi][1] = __float_as_uint(AsH[o1]);
                aH[mi][2] = __float_as_uint(AsH[o0 + 4]);
                aH[mi][3] = __float_as_uint(AsH[o1 + 4]);
                aL[mi][0] = __float_as_uint(AsL[o0]);
                aL[mi][1] = __float_as_uint(AsL[o1]);
                aL[mi][2] = __float_as_uint(AsL[o0 + 4]);
                aL[mi][3] = __float_as_uint(AsL[o1 + 4]);
            }
#pragma unroll
            for (int ni = 0; ni < 8; ni++) {
                int n = nw * 64 + ni * 8 + (lane >> 2);
                int ob0 = (kk + (lane & 3)) * BS_STRIDE + n;
                int ob1 = (kk + 4 + (lane & 3)) * BS_STRIDE + n;
                uint32_t bH0 = __float_as_uint(BsH[ob0]);
                uint32_t bH1 = __float_as_uint(BsH[ob1]);
                uint32_t bL0 = __float_as_uint(BsL[ob0]);
                uint32_t bL1 = __float_as_uint(BsL[ob1]);
                mma_tf32(c[0][ni], aL[0], bH0, bH1);
                mma_tf32(c[1][ni], aL[1], bH0, bH1);
                mma_tf32(c[0][ni], aH[0], bL0, bL1);
                mma_tf32(c[1][ni], aH[1], bL0, bL1);
                mma_tf32(c[0][ni], aH[0], bH0, bH1);
                mma_tf32(c[1][ni], aH[1], bH0, bH1);
            }
        }
        if (ch + 1 < nch) {
            __syncthreads();
            sts_chunk(AsH, AsL, BsH, BsL, tid, ra, rb);
        }
    }

#pragma unroll
    for (int mi = 0; mi < 2; mi++) {
#pragma unroll
        for (int ni = 0; ni < 8; ni++) {
            int row = R0 + mw * 32 + mi * 16 + (lane >> 2);
            int col = nw * 64 + ni * 8 + 2 * (lane & 3);
            *(float2*)(C + (size_t)row * 128 + col) = make_float2(c[mi][ni][0], c[mi][ni][1]);
            *(float2*)(C + (size_t)(row + 8) * 128 + col) = make_float2(c[mi][ni][2], c[mi][ni][3]);
        }
    }
}

// ---------------- CSR gather-aggregate + self loop + bias + relu (4-way unrolled) ----------------
__global__ void __launch_bounds__(256) agg_kernel(
    const float* __restrict__ xw,
    const int* __restrict__ rowstart, const int* __restrict__ degI,
    const int* __restrict__ ecol, const float* __restrict__ dis,
    const float* __restrict__ bias, float* __restrict__ out, int n)
{
    int w = (blockIdx.x * blockDim.x + threadIdx.x) >> 5;
    if (w >= n) return;
    int lane = threadIdx.x & 31;
    int rs = rowstart[w];
    int re = rs + degI[w];
    float4 a0 = make_float4(0.f, 0.f, 0.f, 0.f);
    float4 a1 = make_float4(0.f, 0.f, 0.f, 0.f);
    float4 a2 = make_float4(0.f, 0.f, 0.f, 0.f);
    float4 a3 = make_float4(0.f, 0.f, 0.f, 0.f);
    int i = rs;
    for (; i + 4 <= re; i += 4) {
        int s0 = ecol[i], s1 = ecol[i + 1], s2 = ecol[i + 2], s3 = ecol[i + 3];
        float w0 = dis[s0], w1 = dis[s1], w2 = dis[s2], w3 = dis[s3];
        float4 v0 = *(const float4*)(xw + (size_t)s0 * 128 + lane * 4);
        float4 v1 = *(const float4*)(xw + (size_t)s1 * 128 + lane * 4);
        float4 v2 = *(const float4*)(xw + (size_t)s2 * 128 + lane * 4);
        float4 v3 = *(const float4*)(xw + (size_t)s3 * 128 + lane * 4);
        a0.x = fmaf(v0.x, w0, a0.x); a0.y = fmaf(v0.y, w0, a0.y);
        a0.z = fmaf(v0.z, w0, a0.z); a0.w = fmaf(v0.w, w0, a0.w);
        a1.x = fmaf(v1.x, w1, a1.x); a1.y = fmaf(v1.y, w1, a1.y);
        a1.z = fmaf(v1.z, w1, a1.z); a1.w = fmaf(v1.w, w1, a1.w);
        a2.x = fmaf(v2.x, w2, a2.x); a2.y = fmaf(v2.y, w2, a2.y);
        a2.z = fmaf(v2.z, w2, a2.z); a2.w = fmaf(v2.w, w2, a2.w);
        a3.x = fmaf(v3.x, w3, a3.x); a3.y = fmaf(v3.y, w3, a3.y);
        a3.z = fmaf(v3.z, w3, a3.z); a3.w = fmaf(v3.w, w3, a3.w);
    }
    for (; i < re; i++) {
        int s0 = ecol[i];
        float w0 = dis[s0];
        float4 v0 = *(const float4*)(xw + (size_t)s0 * 128 + lane * 4);
        a0.x = fmaf(v0.x, w0, a0.x); a0.y = fmaf(v0.y, w0, a0.y);
        a0.z = fmaf(v0.z, w0, a0.z); a0.w = fmaf(v0.w, w0, a0.w);
    }
    a0.x += a1.x + a2.x + a3.x;
    a0.y += a1.y + a2.y + a3.y;
    a0.z += a1.z + a2.z + a3.z;
    a0.w += a1.w + a2.w + a3.w;
    float dd = dis[w];
    float sw = dd * dd;
    float4 self = *(const float4*)(xw + (size_t)w * 128 + lane * 4);
    float4 r;
    r.x = fmaxf(fmaf(a0.x, dd, fmaf(self.x, sw, bias[lane * 4 + 0])), 0.f);
    r.y = fmaxf(fmaf(a0.y, dd, fmaf(self.y, sw, bias[lane * 4 + 1])), 0.f);
    r.z = fmaxf(fmaf(a0.z, dd, fmaf(self.z, sw, bias[lane * 4 + 2])), 0.f);
    r.w = fmaxf(fmaf(a0.w, dd, fmaf(self.w, sw, bias[lane * 4 + 3])), 0.f);
    *(float4*)(out + (size_t)w * 128 + lane * 4) = r;
}

// ---------------- attention pool (big, 384 feats) ----------------
__global__ void mean384_kernel() {
    int s = blockIdx.x >> 2, ch = blockIdx.x & 3;
    int f = threadIdx.x;
    int g = s & 63, cl = s >> 6;
    int base = g * NPER + cl * N1_ + ch * 128;
    float acc = 0.f;
#pragma unroll 4
    for (int j = 0; j < 128; j++) acc += xcat_at(base + j, f);
    atomicAdd(&g_mean[s * 384 + f], acc);
}

__global__ void catt_kernel(const float* __restrict__ Wg) {
    __shared__ float m[384];
    int s = blockIdx.x, f = threadIdx.x;
    m[f] = g_mean[s * 384 + f] * (1.f / 512.f);
    __syncthreads();
    float acc = 0.f;
    for (int k = 0; k < 384; k++) acc = fmaf(m[k], Wg[k * 384 + f], acc);
    g_catt[s * 384 + f] = tanhf(acc);
}

// fused alpha + gp: one xcat pass.
__global__ void __launch_bounds__(256) alphagp_kernel() {
    int blk = blockIdx.x;
    int s = blk >> 3, ch = blk & 7;
    int g = s & 63, cl = s >> 6;
    int base = g * NPER + cl * N1_ + ch * 64;
    int wid = threadIdx.x >> 5, lane = threadIdx.x & 31;
    __shared__ float csh[384];
    __shared__ float gpsh[384];
    for (int t = threadIdx.x; t < 384; t += 256) { csh[t] = g_catt[s * 384 + t]; gpsh[t] = 0.f; }
    __syncthreads();
    float acc[12];
#pragma unroll
    for (int q = 0; q < 12; q++) acc[q] = 0.f;
    for (int j = 0; j < 8; j++) {
        int node = base + wid * 8 + j;
        float xv[12];
        float dot = 0.f;
#pragma unroll
        for (int q = 0; q < 12; q++) {
            int f = q * 32 + lane;
            xv[q] = xcat_at(node, f);
            dot = fmaf(xv[q], csh[f], dot);
        }
#pragma unroll
        for (int o = 16; o; o >>= 1) dot += __shfl_xor_sync(0xffffffffu, dot, o);
        float alpha = sigmoidf_(dot);
#pragma unroll
        for (int q = 0; q < 12; q++) acc[q] = fmaf(xv[q], alpha, acc[q]);
    }
#pragma unroll
    for (int q = 0; q < 12; q++) atomicAdd(&gpsh[q * 32 + lane], acc[q]);
    __syncthreads();
    for (int t = threadIdx.x; t < 384; t += 256) atomicAdd(&g_gp[s * 384 + t], gpsh[t]);
}

__global__ void pv_kernel(const float* __restrict__ Wal, const float* __restrict__ bal) {
    __shared__ float in[768];
    int g = blockIdx.x, t = threadIdx.x;
    in[t] = (t < 384) ? g_gp[g * 384 + t] : g_gp[(64 + g) * 384 + (t - 384)];
    __syncthreads();
    float acc = bal[t];
    for (int k = 0; k < 768; k++) acc = fmaf(in[k], Wal[k * 768 + t], acc);
    g_pv[g * 768 + t] = acc;
}

__global__ void pvnorm_kernel() {
    int b = blockIdx.x;
    int cl = b >> 6, g = b & 63;
    int t = threadIdx.x;
    float acc = 0.f;
    for (int k = t; k < 384; k += 128) {
        float v = g_pv[g * 768 + cl * 384 + k];
        acc += v * v;
    }
    __shared__ float red[128];
    red[t] = acc;
    __syncthreads();
    for (int o = 64; o; o >>= 1) {
        if (t < o) red[t] += red[t + o];
        __syncthreads();
    }
    if (!t) g_pvnorm[b] = sqrtf(red[0]);
}

// ---------------- CAG pool ----------------
__global__ void score_kernel() {
    int w = (blockIdx.x * blockDim.x + threadIdx.x) >> 5;
    if (w >= NTOT) return;
    int lane = threadIdx.x & 31;
    int cl = w >> 15;
    int rem = w & 32767;
    int g = rem >> 9, j = rem & 511;
    int node = g * NPER + cl * N1_ + j;
    const float* q = g_pv + g * 768 + cl * 384;
    float acc = 0.f;
    for (int t = lane; t < 384; t += 32) acc += xcat_at(node, t) * q[t];
#pragma unroll
    for (int o = 16; o; o >>= 1) acc += __shfl_xor_sync(0xffffffffu, acc, o);
    if (!lane) g_score[cl][g * 512 + j] = acc / g_pvnorm[cl * 64 + g];
}

__global__ void topk_kernel() {
    int b = blockIdx.x;
    int cl = b >> 6, g = b & 63;
    int j = threadIdx.x;
    __shared__ float s[512];
    s[j] = g_score[cl][g * 512 + j];
    __syncthreads();
    float mys = s[j];
    int rank = 0;
    for (int i = 0; i < 512; i++) {
        float o = s[i];
        rank += (o > mys) || (o == mys && i < j);
    }
    g_map[cl][g * 512 + j] = (rank < KSEL) ? (g * KSEL + rank) : -1;
    if (rank < KSEL) g_perm[cl][g * KSEL + rank] = j;
}

__global__ void gather_kernel() {
    int w = (blockIdx.x * blockDim.x + threadIdx.x) >> 5;
    if (w >= 2 * NPOOL) return;
    int lane = threadIdx.x & 31;
    int cl = w >> 14;
    int r = w & (NPOOL - 1);
    int g = r >> 8;
    int j = g_perm[cl][r];
    int node = g * NPER + cl * N1_ + j;
    float gate = sigmoidf_(g_score[cl][g * 512 + j]);
    float* o = g_pool[cl] + (size_t)r * 384;
    for (int t = lane; t < 384; t += 32) o[t] = xcat_at(node, t) * gate;
}

// ---------------- final attention pool ----------------
__global__ void meanF_kernel() {
    int b = blockIdx.x >> 1, ch = blockIdx.x & 1;
    int cl = b >> 6, g = b & 63;
    int f = threadIdx.x;
    const float* h = g_hP[cl] + ((size_t)g * KSEL + ch * 128) * 128;
    float acc = 0.f;
#pragma unroll 4
    for (int j = 0; j < 128; j++) acc += h[(size_t)j * 128 + f];
    atomicAdd(&g_meanF[cl][g * 128 + f], acc);
}

__global__ void cF_kernel(const float* __restrict__ Wg) {
    int b = blockIdx.x;
    int cl = b >> 6, g = b & 63;
    int f = threadIdx.x;
    __shared__ float m[128];
    m[f] = g_meanF[cl][g * 128 + f] * (1.f / 256.f);
    __syncthreads();
    float acc = 0.f;
    for (int k = 0; k < 128; k++) acc = fmaf(m[k], Wg[k * 128 + f], acc);
    g_cF[cl][g * 128 + f] = tanhf(acc);
}

__global__ void alphaP_kernel() {
    int w = (blockIdx.x * blockDim.x + threadIdx.x) >> 5;
    if (w >= 2 * NPOOL) return;
    int lane = threadIdx.x & 31;
    int cl = w >> 14;
    int r = w & (NPOOL - 1);
    int g = r >> 8;
    const float* h = g_hP[cl] + (size_t)r * 128;
    const float* c = g_cF[cl] + g * 128;
    float acc = 0.f;
    for (int t = lane; t < 128; t += 32) acc += h[t] * c[t];
#pragma unroll
    for (int o = 16; o; o >>= 1) acc += __shfl_xor_sync(0xffffffffu, acc, o);
    if (!lane) g_alphaP[cl][r] = sigmoidf_(acc);
}

__global__ void gfin_kernel() {
    int b = blockIdx.x >> 1, ch = blockIdx.x & 1;
    int cl = b >> 6, g = b & 63;
    int f = threadIdx.x;
    float acc = 0.f;
#pragma unroll 4
    for (int j = 0; j < 128; j++) {
        int r = g * KSEL + ch * 128 + j;
        acc = fmaf(g_hP[cl][(size_t)r * 128 + f], g_alphaP[cl][r], acc);
    }
    atomicAdd(&g_gfin[cl][g * 128 + f], acc);
}

// ---------------- final MLP ----------------
__global__ void mlp_kernel(const float* __restrict__ Wl1, const float* __restrict__ bl1,
                           const float* __restrict__ Wl2, const float* __restrict__ bl2,
                           const float* __restrict__ Wl3, const float* __restrict__ bl3,
                           float* __restrict__ out)
{
    __shared__ float in[256];
    __shared__ float z1[128];
    __shared__ float z2[64];
    int g = blockIdx.x, t = threadIdx.x;
    in[t] = g_gfin[0][g * 128 + t];
    in[128 + t] = g_gfin[1][g * 128 + t];
    __syncthreads();
    float a = bl1[t];
    for (int k = 0; k < 256; k++) a = fmaf(in[k], Wl1[k * 128 + t], a);
    z1[t] = fmaxf(a, 0.f);
    __syncthreads();
    if (t < 64) {
        float a2 = bl2[t];
        for (int k = 0; k < 128; k++) a2 = fmaf(z1[k], Wl2[k * 64 + t], a2);
        z2[t] = fmaxf(a2, 0.f);
    }
    __syncthreads();
    if (t < 2) {
        float a3 = bl3[t];
        for (int k = 0; k < 64; k++) a3 = fmaf(z2[k], Wl3[k * 2 + t], a3);
        out[g * 2 + t] = a3;
    }
}

// ---------------- host orchestration (single stream, graph-capture safe) ----------------
extern "C" void kernel_launch(void* const* d_in, const int* in_sizes, int n_in,
                              void* d_out, int out_size)
{
    const float* x       = (const float*)d_in[0];
    const int*   src_all = (const int*)d_in[1];
    const int*   dst_all = (const int*)d_in[2];
    const int*   src_c[2] = { (const int*)d_in[3], (const int*)d_in[5] };
    const int*   dst_c[2] = { (const int*)d_in[4], (const int*)d_in[6] };
    const float* W1 = (const float*)d_in[7];  const float* b1 = (const float*)d_in[8];
    const float* W2 = (const float*)d_in[9];  const float* b2 = (const float*)d_in[10];
    const float* W3 = (const float*)d_in[11]; const float* b3 = (const float*)d_in[12];
    const float* Wg_att = (const float*)d_in[13];
    const float* Wal = (const float*)d_in[14]; const float* bal = (const float*)d_in[15];
    const float* Wf  = (const float*)d_in[16]; const float* bf  = (const float*)d_in[17];
    const float* Wg_fin = (const float*)d_in[18];
    const float* Wl1 = (const float*)d_in[19]; const float* bl1 = (const float*)d_in[20];
    const float* Wl2 = (const float*)d_in[21]; const float* bl2 = (const float*)d_in[22];
    const float* Wl3 = (const float*)d_in[23]; const float* bl3 = (const float*)d_in[24];

    void* p;
    cudaGetSymbolAddress(&p, g_h0);        float* h0   = (float*)p;
    cudaGetSymbolAddress(&p, g_h1);        float* h1   = (float*)p;
    cudaGetSymbolAddress(&p, g_h2);        float* h2   = (float*)p;
    cudaGetSymbolAddress(&p, g_xw);        float* xw   = (float*)p;
    cudaGetSymbolAddress(&p, g_dis);       float* dis  = (float*)p;
    cudaGetSymbolAddress(&p, g_degI);      int* degI   = (int*)p;
    cudaGetSymbolAddress(&p, g_rowstart);  int* rowst  = (int*)p;
    cudaGetSymbolAddress(&p, g_cursor);    int* cursor = (int*)p;
    cudaGetSymbolAddress(&p, g_ecol);      int* ecol   = (int*)p;
    cudaGetSymbolAddress(&p, g_ctr);       int* ctr    = (int*)p;
    cudaGetSymbolAddress(&p, g_pool);      float* pool = (float*)p;
    cudaGetSymbolAddress(&p, g_degPI);     int* degPI  = (int*)p;
    cudaGetSymbolAddress(&p, g_rowstartP); int* rowstP = (int*)p;
    cudaGetSymbolAddress(&p, g_cursorP);   int* cursP  = (int*)p;
    cudaGetSymbolAddress(&p, g_ecolP);     int* ecolP  = (int*)p;
    cudaGetSymbolAddress(&p, g_disP);      float* disP = (float*)p;
    cudaGetSymbolAddress(&p, g_xwP);       float* xwP  = (float*)p;
    cudaGetSymbolAddress(&p, g_hP);        float* hP   = (float*)p;

    static bool attr_done = false;
    if (!attr_done) {
        cudaFuncSetAttribute(gemm_tf32, cudaFuncAttributeMaxDynamicSharedMemorySize, GEMM_SMEM);
        attr_done = true;
    }

    // launches 1-3, then #4 = the big tf32 GEMM (ncu window lands on the 4th launch)
    zero_all_kernel<<<256, 256>>>();                                         // 1
    degi_kernel<<<E_ALL / 256, 256>>>(dst_all, degI, E_ALL);                 // 2
    assign_kernel<<<NTOT / 256, 256>>>(degI, rowst, cursor, dis, NTOT, ctr); // 3
    gemm_tf32<<<NTOT / 128, 256, GEMM_SMEM>>>(x, W1, xw, 128);               // 4  <-- profiled

    place_kernel<<<E_ALL / 256, 256>>>(src_all, dst_all, cursor, ecol, E_ALL);

    // ---- 3 GCN layers ----
    agg_kernel<<<NTOT / 8, 256>>>(xw, rowst, degI, ecol, dis, b1, h0, NTOT);
    gemm_tf32<<<NTOT / 128, 256, GEMM_SMEM>>>(h0, W2, xw, 128);
    agg_kernel<<<NTOT / 8, 256>>>(xw, rowst, degI, ecol, dis, b2, h1, NTOT);
    gemm_tf32<<<NTOT / 128, 256, GEMM_SMEM>>>(h1, W3, xw, 128);
    agg_kernel<<<NTOT / 8, 256>>>(xw, rowst, degI, ecol, dis, b3, h2, NTOT);

    // ---- dual attention pooling ----
    mean384_kernel<<<512, 384>>>();
    catt_kernel<<<128, 384>>>(Wg_att);
    alphagp_kernel<<<1024, 256>>>();
    pv_kernel<<<64, 768>>>(Wal, bal);
    pvnorm_kernel<<<128, 128>>>();

    // ---- CAG pool ----
    score_kernel<<<NTOT / 8, 256>>>();
    topk_kernel<<<128, 512>>>();
    gather_kernel<<<(2 * NPOOL) / 8, 256>>>();

    // ---- pooled CSR (combined over both clusters, scan-free) ----
    degPI2_kernel<<<(2 * E_C) / 256, 256>>>(src_c[0], dst_c[0], src_c[1], dst_c[1]);
    assign_kernel<<<(2 * NPOOL) / 256, 256>>>(degPI, rowstP, cursP, disP, 2 * NPOOL, ctr + 1);
    placeP2_kernel<<<(2 * E_C) / 256, 256>>>(src_c[0], dst_c[0], src_c[1], dst_c[1]);

    // ---- pooled GCN (both clusters in one GEMM + one agg) ----
    gemm_tf32<<<(2 * NPOOL) / 128, 256, GEMM_SMEM>>>(pool, Wf, xwP, 384);
    agg_kernel<<<(2 * NPOOL) / 8, 256>>>(xwP, rowstP, degPI, ecolP, disP, bf, hP, 2 * NPOOL);

    // ---- final attention pools + MLP head ----
    meanF_kernel<<<256, 128>>>();
    cF_kernel<<<128, 128>>>(Wg_fin);
    alphaP_kernel<<<(2 * NPOOL) / 8, 256>>>();
    gfin_kernel<<<256, 128>>>();
    mlp_kernel<<<64, 128>>>(Wl1, bl1, Wl2, bl2, Wl3, bl3, (float*)d_out);
}

// round 14
// speedup vs baseline: 1.1813x; 1.0591x over previous
#include <cuda_runtime.h>
#include <math.h>
#include <stdint.h>

// Problem constants
#define B_      64
#define N1_     512
#define N2_     512
#define NPER    1024
#define NTOT    65536
#define KSEL    256
#define NPOOL   16384
#define E_ALL   1048576
#define E_C     524288

// ---------------- scratch ----------------
__device__ float g_h0[(size_t)NTOT * 128];
__device__ float g_h1[(size_t)NTOT * 128];
__device__ float g_h2[(size_t)NTOT * 128];
__device__ float g_xw[(size_t)NTOT * 128];
__device__ float g_dis[NTOT];

// CSR for the big graph
__device__ int g_degI[NTOT];
__device__ int g_rowstart[NTOT];
__device__ int g_cursor[NTOT];
__device__ int g_ecol[E_ALL];
__device__ int g_ctr[2];

__device__ float g_mean[128 * 384];
__device__ float g_catt[128 * 384];
__device__ float g_gp[128 * 384];
__device__ float g_pv[64 * 768];
__device__ float g_pvnorm[128];

__device__ float g_score[2][B_ * N1_];
__device__ int   g_map[2][B_ * N1_];
__device__ int   g_perm[2][B_ * KSEL];

// pooled CSR (combined over both clusters)
__device__ int   g_degPI[2 * NPOOL];
__device__ int   g_rowstartP[2 * NPOOL];
__device__ int   g_cursorP[2 * NPOOL];
__device__ int   g_ecolP[2 * E_C];
__device__ float g_disP[2 * NPOOL];

__device__ float g_xwP[(size_t)2 * NPOOL * 128];
__device__ float g_hP[2][(size_t)NPOOL * 128];

__device__ float g_meanF[2][B_ * 128];
__device__ float g_cF[2][B_ * 128];
__device__ float g_gfin[2][B_ * 128];

__device__ __forceinline__ float xcat_at(int node, int f) {
    const float* H = (f < 128) ? g_h0 : ((f < 256) ? g_h1 : g_h2);
    return H[(size_t)node * 128 + (f & 127)];
}
__device__ __forceinline__ float sigmoidf_(float x) { return 1.f / (1.f + expf(-x)); }

// ---------------- zero everything that accumulates ----------------
__global__ void zero_all_kernel() {
    const int NM = 128 * 384;
    int stride = gridDim.x * blockDim.x;
    for (int i = blockIdx.x * blockDim.x + threadIdx.x;
         i < NTOT + 2 * NPOOL + 2 + 2 * NM + 2 * 2 * B_ * 128; i += stride) {
        int j = i;
        if (j < NTOT) { g_degI[j] = 0; continue; }
        j -= NTOT;
        if (j < 2 * NPOOL) { g_degPI[j] = 0; continue; }
        j -= 2 * NPOOL;
        if (j < 2) { g_ctr[j] = 0; continue; }
        j -= 2;
        if (j < NM) { g_mean[j] = 0.f; continue; }
        j -= NM;
        if (j < NM) { g_gp[j] = 0.f; continue; }
        j -= NM;
        if (j < 2 * B_ * 128) { ((float*)g_meanF)[j] = 0.f; continue; }
        j -= 2 * B_ * 128;
        ((float*)g_gfin)[j] = 0.f;
    }
}

__global__ void degi_kernel(const int* __restrict__ dst, int* __restrict__ deg, int E) {
    int e = blockIdx.x * blockDim.x + threadIdx.x;
    if (e < E) atomicAdd(&deg[dst[e]], 1);
}

// combined pooled degree count over both clusters
__global__ void degPI2_kernel(const int* __restrict__ src0, const int* __restrict__ dst0,
                              const int* __restrict__ src1, const int* __restrict__ dst1) {
    int e = blockIdx.x * blockDim.x + threadIdx.x;
    if (e < E_C) {
        int r = g_map[0][src0[e]], c = g_map[0][dst0[e]];
        if (r >= 0 && c >= 0) atomicAdd(&g_degPI[c], 1);
    } else {
        e -= E_C;
        int r = g_map[1][src1[e]], c = g_map[1][dst1[e]];
        if (r >= 0 && c >= 0) atomicAdd(&g_degPI[NPOOL + c], 1);
    }
}

// rowstart assignment without scans: order-free atomic range grab.
__global__ void assign_kernel(const int* __restrict__ deg, int* __restrict__ rowstart,
                              int* __restrict__ cursor, float* __restrict__ dis,
                              int n, int* __restrict__ ctr) {
    int i = blockIdx.x * blockDim.x + threadIdx.x;
    if (i >= n) return;
    int d = deg[i];
    int rs = atomicAdd(ctr, d);
    rowstart[i] = rs;
    cursor[i] = rs;
    dis[i] = rsqrtf((float)d + 1.f);
}

// ---------------- CSR edge placement (cursor pre-seeded with rowstart) ----------------
__global__ void place_kernel(const int* __restrict__ src, const int* __restrict__ dst,
                             int* __restrict__ cursor, int* __restrict__ ecol, int E) {
    int e = blockIdx.x * blockDim.x + threadIdx.x;
    if (e >= E) return;
    int pos = atomicAdd(&cursor[dst[e]], 1);
    ecol[pos] = src[e];
}
// combined pooled placement over both clusters
__global__ void placeP2_kernel(const int* __restrict__ src0, const int* __restrict__ dst0,
                               const int* __restrict__ src1, const int* __restrict__ dst1) {
    int e = blockIdx.x * blockDim.x + threadIdx.x;
    int cl = 0, off = 0;
    const int* S = src0;
    const int* D = dst0;
    if (e >= E_C) { e -= E_C; S = src1; D = dst1; cl = 1; off = NPOOL; }
    int r = g_map[cl][S[e]], c = g_map[cl][D[e]];
    if (r < 0 || c < 0) return;
    int pos = atomicAdd(&g_cursorP[c + off], 1);
    g_ecolP[pos] = r + off;
}

// ============ 3xTF32 tensor-core GEMM (separate hi/lo planes) ============
__device__ __forceinline__ uint32_t f2tf32(float x) {
    uint32_t y;
    asm("cvt.rna.tf32.f32 %0, %1;" : "=r"(y) : "f"(x));
    return y;
}
__device__ __forceinline__ void mma_tf32(float* c, const uint32_t* a, uint32_t b0, uint32_t b1) {
    asm volatile("mma.sync.aligned.m16n8k8.row.col.f32.tf32.tf32.f32 "
                 "{%0,%1,%2,%3}, {%4,%5,%6,%7}, {%8,%9}, {%0,%1,%2,%3};"
                 : "+f"(c[0]), "+f"(c[1]), "+f"(c[2]), "+f"(c[3])
                 : "r"(a[0]), "r"(a[1]), "r"(a[2]), "r"(a[3]), "r"(b0), "r"(b1));
}

#define AS_STRIDE 36
#define BS_STRIDE 136
#define GEMM_SMEM ((2 * 128 * AS_STRIDE + 2 * 32 * BS_STRIDE) * 4)  // 71680 B

__device__ __forceinline__ void split_store(float* hiP, float* loP, float v) {
    float h = __uint_as_float(f2tf32(v));
    *hiP = h;
    *loP = __uint_as_float(f2tf32(v - h));
}

__device__ __forceinline__ void sts_chunk(float* AsH, float* AsL, float* BsH, float* BsL,
                                          int tid, const float4* ra, const float4* rb) {
#pragma unroll
    for (int i = 0; i < 4; i++) {
        int q = tid + i * 256;
        int r = q >> 3, c4 = (q & 7) << 2;
        int o = r * AS_STRIDE + c4;
        split_store(AsH + o + 0, AsL + o + 0, ra[i].x);
        split_store(AsH + o + 1, AsL + o + 1, ra[i].y);
        split_store(AsH + o + 2, AsL + o + 2, ra[i].z);
        split_store(AsH + o + 3, AsL + o + 3, ra[i].w);
    }
#pragma unroll
    for (int i = 0; i < 4; i++) {
        int q = tid + i * 256;
        int r = q >> 5, c4 = (q & 31) << 2;
        int o = r * BS_STRIDE + c4;
        split_store(BsH + o + 0, BsL + o + 0, rb[i].x);
        split_store(BsH + o + 1, BsL + o + 1, rb[i].y);
        split_store(BsH + o + 2, BsL + o + 2, rb[i].z);
        split_store(BsH + o + 3, BsL + o + 3, rb[i].w);
    }
}

// shared mainloop body: assumes ra/rb for chunk 0 already staged in smem
__device__ __forceinline__ void gemm_mainloop_and_epilogue(
    float* AsH, float* AsL, float* BsH, float* BsL,
    int tid, int lane, int mw, int nw, int R0, int nch,
    float4* ra, float4* rb, bool prefetched_valid,
    const float4* nextA_dummy, float* C)
{
    // (not used; kept simple by inlining in each kernel)
}

__device__ __forceinline__ void ldg_chunk_dense(const float* __restrict__ A, const float* __restrict__ W,
                                                int K, int R0, int k0, int tid,
                                                float4* ra, float4* rb) {
#pragma unroll
    for (int i = 0; i < 4; i++) {
        int q = tid + i * 256;
        int r = q >> 3, c4 = (q & 7) << 2;
        ra[i] = *(const float4*)(A + (size_t)(R0 + r) * K + k0 + c4);
    }
#pragma unroll
    for (int i = 0; i < 4; i++) {
        int q = tid + i * 256;
        int r = q >> 5, c4 = (q & 31) << 2;
        rb[i] = *(const float4*)(W + (size_t)(k0 + r) * 128 + c4);
    }
}

__device__ __forceinline__ void gemm_compute_chunk(
    const float* AsH, const float* AsL, const float* BsH, const float* BsL,
    int lane, int mw, int nw, float c[2][8][4])
{
#pragma unroll
    for (int step = 0; step < 4; step++) {
        int kk = step * 8;
        uint32_t aH[2][4], aL[2][4];
#pragma unroll
        for (int mi = 0; mi < 2; mi++) {
            int r = mw * 32 + mi * 16 + (lane >> 2);
            int cc = kk + (lane & 3);
            int o0 = r * AS_STRIDE + cc, o1 = (r + 8) * AS_STRIDE + cc;
            aH[mi][0] = __float_as_uint(AsH[o0]);
            aH[mi][1] = __float_as_uint(AsH[o1]);
            aH[mi][2] = __float_as_uint(AsH[o0 + 4]);
            aH[mi][3] = __float_as_uint(AsH[o1 + 4]);
            aL[mi][0] = __float_as_uint(AsL[o0]);
            aL[mi][1] = __float_as_uint(AsL[o1]);
            aL[mi][2] = __float_as_uint(AsL[o0 + 4]);
            aL[mi][3] = __float_as_uint(AsL[o1 + 4]);
        }
#pragma unroll
        for (int ni = 0; ni < 8; ni++) {
            int n = nw * 64 + ni * 8 + (lane >> 2);
            int ob0 = (kk + (lane & 3)) * BS_STRIDE + n;
            int ob1 = (kk + 4 + (lane & 3)) * BS_STRIDE + n;
            uint32_t bH0 = __float_as_uint(BsH[ob0]);
            uint32_t bH1 = __float_as_uint(BsH[ob1]);
            uint32_t bL0 = __float_as_uint(BsL[ob0]);
            uint32_t bL1 = __float_as_uint(BsL[ob1]);
            mma_tf32(c[0][ni], aL[0], bH0, bH1);
            mma_tf32(c[1][ni], aL[1], bH0, bH1);
            mma_tf32(c[0][ni], aH[0], bL0, bL1);
            mma_tf32(c[1][ni], aH[1], bL0, bL1);
            mma_tf32(c[0][ni], aH[0], bH0, bH1);
            mma_tf32(c[1][ni], aH[1], bH0, bH1);
        }
    }
}

__device__ __forceinline__ void gemm_epilogue(int lane, int mw, int nw, int R0,
                                              float c[2][8][4], float* __restrict__ C)
{
#pragma unroll
    for (int mi = 0; mi < 2; mi++) {
#pragma unroll
        for (int ni = 0; ni < 8; ni++) {
            int row = R0 + mw * 32 + mi * 16 + (lane >> 2);
            int col = nw * 64 + ni * 8 + 2 * (lane & 3);
            *(float2*)(C + (size_t)row * 128 + col) = make_float2(c[mi][ni][0], c[mi][ni][1]);
            *(float2*)(C + (size_t)(row + 8) * 128 + col) = make_float2(c[mi][ni][2], c[mi][ni][3]);
        }
    }
}

__global__ void __launch_bounds__(256, 2) gemm_tf32(
    const float* __restrict__ A, const float* __restrict__ W,
    float* __restrict__ C, int K)
{
    extern __shared__ float sm[];
    float* AsH = sm;
    float* AsL = AsH + 128 * AS_STRIDE;
    float* BsH = AsL + 128 * AS_STRIDE;
    float* BsL = BsH + 32 * BS_STRIDE;

    int tid = threadIdx.x, lane = tid & 31, w = tid >> 5;
    int mw = w >> 1, nw = w & 1;
    int R0 = blockIdx.x * 128;

    float c[2][8][4];
#pragma unroll
    for (int mi = 0; mi < 2; mi++)
#pragma unroll
        for (int ni = 0; ni < 8; ni++)
#pragma unroll
            for (int k = 0; k < 4; k++) c[mi][ni][k] = 0.f;

    float4 ra[4], rb[4];
    ldg_chunk_dense(A, W, K, R0, 0, tid, ra, rb);
    sts_chunk(AsH, AsL, BsH, BsL, tid, ra, rb);

    int nch = K >> 5;
    for (int ch = 0; ch < nch; ch++) {
        __syncthreads();
        if (ch + 1 < nch) ldg_chunk_dense(A, W, K, R0, (ch + 1) << 5, tid, ra, rb);
        gemm_compute_chunk(AsH, AsL, BsH, BsL, lane, mw, nw, c);
        if (ch + 1 < nch) {
            __syncthreads();
            sts_chunk(AsH, AsL, BsH, BsL, tid, ra, rb);
        }
    }
    gemm_epilogue(lane, mw, nw, R0, c, C);
}

// ---- pooled GEMM with fused gather: A[row][k] = xcat(node(row),k) * gate(row) ----
// K = 384 fixed; rows cover 2*NPOOL.
__global__ void __launch_bounds__(256, 2) gemm_pool(
    const float* __restrict__ W, float* __restrict__ C)
{
    extern __shared__ float sm[];
    float* AsH = sm;
    float* AsL = AsH + 128 * AS_STRIDE;
    float* BsH = AsL + 128 * AS_STRIDE;
    float* BsL = BsH + 32 * BS_STRIDE;

    int tid = threadIdx.x, lane = tid & 31, w = tid >> 5;
    int mw = w >> 1, nw = w & 1;
    int R0 = blockIdx.x * 128;

    // per-thread source-row metadata (4 A rows per thread, fixed across chunks)
    const float* Hs[3] = { g_h0, g_h1, g_h2 };
    const float* rowPtrBase[4];   // node*128 within layer-0 plane; add layer offset via Hs select
    int nodeR[4];
    float gateR[4];
#pragma unroll
    for (int i = 0; i < 4; i++) {
        int q = tid + i * 256;
        int r = q >> 3;
        int row = R0 + r;
        int cl = row >> 14;
        int rr = row & (NPOOL - 1);
        int g = rr >> 8;
        int j = g_perm[cl][rr];
        nodeR[i] = g * NPER + cl * N1_ + j;
        gateR[i] = sigmoidf_(g_score[cl][g * 512 + j]);
        rowPtrBase[i] = 0;  // unused
    }

    float c[2][8][4];
#pragma unroll
    for (int mi = 0; mi < 2; mi++)
#pragma unroll
        for (int ni = 0; ni < 8; ni++)
#pragma unroll
            for (int k = 0; k < 4; k++) c[mi][ni][k] = 0.f;

    float4 ra[4], rb[4];
    // chunk loader (A indirect, gated)
    auto ldg_pool = [&](int k0) {
        const float* H = Hs[k0 >> 7];
        int kloc = k0 & 127;
#pragma unroll
        for (int i = 0; i < 4; i++) {
            int q = tid + i * 256;
            int c4 = (q & 7) << 2;
            float4 v = *(const float4*)(H + (size_t)nodeR[i] * 128 + kloc + c4);
            float gt = gateR[i];
            v.x *= gt; v.y *= gt; v.z *= gt; v.w *= gt;
            ra[i] = v;
        }
#pragma unroll
        for (int i = 0; i < 4; i++) {
            int q = tid + i * 256;
            int r = q >> 5, c4 = (q & 31) << 2;
            rb[i] = *(const float4*)(W + (size_t)(k0 + r) * 128 + c4);
        }
    };

    ldg_pool(0);
    sts_chunk(AsH, AsL, BsH, BsL, tid, ra, rb);

    const int nch = 384 >> 5;   // 12
    for (int ch = 0; ch < nch; ch++) {
        __syncthreads();
        if (ch + 1 < nch) ldg_pool((ch + 1) << 5);
        gemm_compute_chunk(AsH, AsL, BsH, BsL, lane, mw, nw, c);
        if (ch + 1 < nch) {
            __syncthreads();
            sts_chunk(AsH, AsL, BsH, BsL, tid, ra, rb);
        }
    }
    gemm_epilogue(lane, mw, nw, R0, c, C);
}

// ---------------- CSR gather-aggregate + self loop + bias + relu (4-way unrolled) ----------------
__global__ void __launch_bounds__(256) agg_kernel(
    const float* __restrict__ xw,
    const int* __restrict__ rowstart, const int* __restrict__ degI,
    const int* __restrict__ ecol, const float* __restrict__ dis,
    const float* __restrict__ bias, float* __restrict__ out, int n)
{
    int w = (blockIdx.x * blockDim.x + threadIdx.x) >> 5;
    if (w >= n) return;
    int lane = threadIdx.x & 31;
    int rs = rowstart[w];
    int re = rs + degI[w];
    float4 a0 = make_float4(0.f, 0.f, 0.f, 0.f);
    float4 a1 = make_float4(0.f, 0.f, 0.f, 0.f);
    float4 a2 = make_float4(0.f, 0.f, 0.f, 0.f);
    float4 a3 = make_float4(0.f, 0.f, 0.f, 0.f);
    int i = rs;
    for (; i + 4 <= re; i += 4) {
        int s0 = ecol[i], s1 = ecol[i + 1], s2 = ecol[i + 2], s3 = ecol[i + 3];
        float w0 = dis[s0], w1 = dis[s1], w2 = dis[s2], w3 = dis[s3];
        float4 v0 = *(const float4*)(xw + (size_t)s0 * 128 + lane * 4);
        float4 v1 = *(const float4*)(xw + (size_t)s1 * 128 + lane * 4);
        float4 v2 = *(const float4*)(xw + (size_t)s2 * 128 + lane * 4);
        float4 v3 = *(const float4*)(xw + (size_t)s3 * 128 + lane * 4);
        a0.x = fmaf(v0.x, w0, a0.x); a0.y = fmaf(v0.y, w0, a0.y);
        a0.z = fmaf(v0.z, w0, a0.z); a0.w = fmaf(v0.w, w0, a0.w);
        a1.x = fmaf(v1.x, w1, a1.x); a1.y = fmaf(v1.y, w1, a1.y);
        a1.z = fmaf(v1.z, w1, a1.z); a1.w = fmaf(v1.w, w1, a1.w);
        a2.x = fmaf(v2.x, w2, a2.x); a2.y = fmaf(v2.y, w2, a2.y);
        a2.z = fmaf(v2.z, w2, a2.z); a2.w = fmaf(v2.w, w2, a2.w);
        a3.x = fmaf(v3.x, w3, a3.x); a3.y = fmaf(v3.y, w3, a3.y);
        a3.z = fmaf(v3.z, w3, a3.z); a3.w = fmaf(v3.w, w3, a3.w);
    }
    for (; i < re; i++) {
        int s0 = ecol[i];
        float w0 = dis[s0];
        float4 v0 = *(const float4*)(xw + (size_t)s0 * 128 + lane * 4);
        a0.x = fmaf(v0.x, w0, a0.x); a0.y = fmaf(v0.y, w0, a0.y);
        a0.z = fmaf(v0.z, w0, a0.z); a0.w = fmaf(v0.w, w0, a0.w);
    }
    a0.x += a1.x + a2.x + a3.x;
    a0.y += a1.y + a2.y + a3.y;
    a0.z += a1.z + a2.z + a3.z;
    a0.w += a1.w + a2.w + a3.w;
    float dd = dis[w];
    float sw = dd * dd;
    float4 self = *(const float4*)(xw + (size_t)w * 128 + lane * 4);
    float4 r;
    r.x = fmaxf(fmaf(a0.x, dd, fmaf(self.x, sw, bias[lane * 4 + 0])), 0.f);
    r.y = fmaxf(fmaf(a0.y, dd, fmaf(self.y, sw, bias[lane * 4 + 1])), 0.f);
    r.z = fmaxf(fmaf(a0.z, dd, fmaf(self.z, sw, bias[lane * 4 + 2])), 0.f);
    r.w = fmaxf(fmaf(a0.w, dd, fmaf(self.w, sw, bias[lane * 4 + 3])), 0.f);
    *(float4*)(out + (size_t)w * 128 + lane * 4) = r;
}

// ---------------- attention pool (big, 384 feats) ----------------
__global__ void mean384_kernel() {
    int s = blockIdx.x >> 2, ch = blockIdx.x & 3;
    int f = threadIdx.x;
    int g = s & 63, cl = s >> 6;
    int base = g * NPER + cl * N1_ + ch * 128;
    float acc = 0.f;
#pragma unroll 4
    for (int j = 0; j < 128; j++) acc += xcat_at(base + j, f);
    atomicAdd(&g_mean[s * 384 + f], acc);
}

__global__ void catt_kernel(const float* __restrict__ Wg) {
    __shared__ float m[384];
    int s = blockIdx.x, f = threadIdx.x;
    m[f] = g_mean[s * 384 + f] * (1.f / 512.f);
    __syncthreads();
    float acc = 0.f;
    for (int k = 0; k < 384; k++) acc = fmaf(m[k], Wg[k * 384 + f], acc);
    g_catt[s * 384 + f] = tanhf(acc);
}

// fused alpha + gp: one xcat pass.
__global__ void __launch_bounds__(256) alphagp_kernel() {
    int blk = blockIdx.x;
    int s = blk >> 3, ch = blk & 7;
    int g = s & 63, cl = s >> 6;
    int base = g * NPER + cl * N1_ + ch * 64;
    int wid = threadIdx.x >> 5, lane = threadIdx.x & 31;
    __shared__ float csh[384];
    __shared__ float gpsh[384];
    for (int t = threadIdx.x; t < 384; t += 256) { csh[t] = g_catt[s * 384 + t]; gpsh[t] = 0.f; }
    __syncthreads();
    float acc[12];
#pragma unroll
    for (int q = 0; q < 12; q++) acc[q] = 0.f;
    for (int j = 0; j < 8; j++) {
        int node = base + wid * 8 + j;
        float xv[12];
        float dot = 0.f;
#pragma unroll
        for (int q = 0; q < 12; q++) {
            int f = q * 32 + lane;
            xv[q] = xcat_at(node, f);
            dot = fmaf(xv[q], csh[f], dot);
        }
#pragma unroll
        for (int o = 16; o; o >>= 1) dot += __shfl_xor_sync(0xffffffffu, dot, o);
        float alpha = sigmoidf_(dot);
#pragma unroll
        for (int q = 0; q < 12; q++) acc[q] = fmaf(xv[q], alpha, acc[q]);
    }
#pragma unroll
    for (int q = 0; q < 12; q++) atomicAdd(&gpsh[q * 32 + lane], acc[q]);
    __syncthreads();
    for (int t = threadIdx.x; t < 384; t += 256) atomicAdd(&g_gp[s * 384 + t], gpsh[t]);
}

__global__ void pv_kernel(const float* __restrict__ Wal, const float* __restrict__ bal) {
    __shared__ float in[768];
    int g = blockIdx.x, t = threadIdx.x;
    in[t] = (t < 384) ? g_gp[g * 384 + t] : g_gp[(64 + g) * 384 + (t - 384)];
    __syncthreads();
    float acc = bal[t];
    for (int k = 0; k < 768; k++) acc = fmaf(in[k], Wal[k * 768 + t], acc);
    g_pv[g * 768 + t] = acc;
}

__global__ void pvnorm_kernel() {
    int b = blockIdx.x;
    int cl = b >> 6, g = b & 63;
    int t = threadIdx.x;
    float acc = 0.f;
    for (int k = t; k < 384; k += 128) {
        float v = g_pv[g * 768 + cl * 384 + k];
        acc += v * v;
    }
    __shared__ float red[128];
    red[t] = acc;
    __syncthreads();
    for (int o = 64; o; o >>= 1) {
        if (t < o) red[t] += red[t + o];
        __syncthreads();
    }
    if (!t) g_pvnorm[b] = sqrtf(red[0]);
}

// ---------------- CAG pool ----------------
__global__ void score_kernel() {
    int w = (blockIdx.x * blockDim.x + threadIdx.x) >> 5;
    if (w >= NTOT) return;
    int lane = threadIdx.x & 31;
    int cl = w >> 15;
    int rem = w & 32767;
    int g = rem >> 9, j = rem & 511;
    int node = g * NPER + cl * N1_ + j;
    const float* q = g_pv + g * 768 + cl * 384;
    float acc = 0.f;
    for (int t = lane; t < 384; t += 32) acc += xcat_at(node, t) * q[t];
#pragma unroll
    for (int o = 16; o; o >>= 1) acc += __shfl_xor_sync(0xffffffffu, acc, o);
    if (!lane) g_score[cl][g * 512 + j] = acc / g_pvnorm[cl * 64 + g];
}

__global__ void topk_kernel() {
    int b = blockIdx.x;
    int cl = b >> 6, g = b & 63;
    int j = threadIdx.x;
    __shared__ float s[512];
    s[j] = g_score[cl][g * 512 + j];
    __syncthreads();
    float mys = s[j];
    int rank = 0;
    for (int i = 0; i < 512; i++) {
        float o = s[i];
        rank += (o > mys) || (o == mys && i < j);
    }
    g_map[cl][g * 512 + j] = (rank < KSEL) ? (g * KSEL + rank) : -1;
    if (rank < KSEL) g_perm[cl][g * KSEL + rank] = j;
}

// ---------------- final attention pool ----------------
__global__ void meanF_kernel() {
    int b = blockIdx.x >> 1, ch = blockIdx.x & 1;
    int cl = b >> 6, g = b & 63;
    int f = threadIdx.x;
    const float* h = g_hP[cl] + ((size_t)g * KSEL + ch * 128) * 128;
    float acc = 0.f;
#pragma unroll 4
    for (int j = 0; j < 128; j++) acc += h[(size_t)j * 128 + f];
    atomicAdd(&g_meanF[cl][g * 128 + f], acc);
}

__global__ void cF_kernel(const float* __restrict__ Wg) {
    int b = blockIdx.x;
    int cl = b >> 6, g = b & 63;
    int f = threadIdx.x;
    __shared__ float m[128];
    m[f] = g_meanF[cl][g * 128 + f] * (1.f / 256.f);
    __syncthreads();
    float acc = 0.f;
    for (int k = 0; k < 128; k++) acc = fmaf(m[k], Wg[k * 128 + f], acc);
    g_cF[cl][g * 128 + f] = tanhf(acc);
}

// fused alphaP + gfin: one hP pass.
// grid 512: cl = blk>>8, within = blk&255, g = within>>2, ch = within&3 (64 rows per block)
__global__ void __launch_bounds__(256) alphagfin_kernel() {
    int blk = blockIdx.x;
    int cl = blk >> 8;
    int within = blk & 255;
    int g = within >> 2, ch = within & 3;
    int baseRow = g * KSEL + ch * 64;
    int wid = threadIdx.x >> 5, lane = threadIdx.x & 31;
    __shared__ float csh[128];
    __shared__ float accsh[128];
    if (threadIdx.x < 128) {
        csh[threadIdx.x] = g_cF[cl][g * 128 + threadIdx.x];
        accsh[threadIdx.x] = 0.f;
    }
    __syncthreads();
    float acc[4];
#pragma unroll
    for (int q = 0; q < 4; q++) acc[q] = 0.f;
    for (int j = 0; j < 8; j++) {
        int row = baseRow + wid * 8 + j;
        const float* h = g_hP[cl] + (size_t)row * 128;
        float hv[4];
        float dot = 0.f;
#pragma unroll
        for (int q = 0; q < 4; q++) {
            int f = q * 32 + lane;
            hv[q] = h[f];
            dot = fmaf(hv[q], csh[f], dot);
        }
#pragma unroll
        for (int o = 16; o; o >>= 1) dot += __shfl_xor_sync(0xffffffffu, dot, o);
        float alpha = sigmoidf_(dot);
#pragma unroll
        for (int q = 0; q < 4; q++) acc[q] = fmaf(hv[q], alpha, acc[q]);
    }
#pragma unroll
    for (int q = 0; q < 4; q++) atomicAdd(&accsh[q * 32 + lane], acc[q]);
    __syncthreads();
    if (threadIdx.x < 128) atomicAdd(&g_gfin[cl][g * 128 + threadIdx.x], accsh[threadIdx.x]);
}

// ---------------- final MLP ----------------
__global__ void mlp_kernel(const float* __restrict__ Wl1, const float* __restrict__ bl1,
                           const float* __restrict__ Wl2, const float* __restrict__ bl2,
                           const float* __restrict__ Wl3, const float* __restrict__ bl3,
                           float* __restrict__ out)
{
    __shared__ float in[256];
    __shared__ float z1[128];
    __shared__ float z2[64];
    int g = blockIdx.x, t = threadIdx.x;
    in[t] = g_gfin[0][g * 128 + t];
    in[128 + t] = g_gfin[1][g * 128 + t];
    __syncthreads();
    float a = bl1[t];
    for (int k = 0; k < 256; k++) a = fmaf(in[k], Wl1[k * 128 + t], a);
    z1[t] = fmaxf(a, 0.f);
    __syncthreads();
    if (t < 64) {
        float a2 = bl2[t];
        for (int k = 0; k < 128; k++) a2 = fmaf(z1[k], Wl2[k * 64 + t], a2);
        z2[t] = fmaxf(a2, 0.f);
    }
    __syncthreads();
    if (t < 2) {
        float a3 = bl3[t];
        for (int k = 0; k < 64; k++) a3 = fmaf(z2[k], Wl3[k * 2 + t], a3);
        out[g * 2 + t] = a3;
    }
}

// ---------------- host orchestration (single stream, graph-capture safe) ----------------
extern "C" void kernel_launch(void* const* d_in, const int* in_sizes, int n_in,
                              void* d_out, int out_size)
{
    const float* x       = (const float*)d_in[0];
    const int*   src_all = (const int*)d_in[1];
    const int*   dst_all = (const int*)d_in[2];
    const int*   src_c[2] = { (const int*)d_in[3], (const int*)d_in[5] };
    const int*   dst_c[2] = { (const int*)d_in[4], (const int*)d_in[6] };
    const float* W1 = (const float*)d_in[7];  const float* b1 = (const float*)d_in[8];
    const float* W2 = (const float*)d_in[9];  const float* b2 = (const float*)d_in[10];
    const float* W3 = (const float*)d_in[11]; const float* b3 = (const float*)d_in[12];
    const float* Wg_att = (const float*)d_in[13];
    const float* Wal = (const float*)d_in[14]; const float* bal = (const float*)d_in[15];
    const float* Wf  = (const float*)d_in[16]; const float* bf  = (const float*)d_in[17];
    const float* Wg_fin = (const float*)d_in[18];
    const float* Wl1 = (const float*)d_in[19]; const float* bl1 = (const float*)d_in[20];
    const float* Wl2 = (const float*)d_in[21]; const float* bl2 = (const float*)d_in[22];
    const float* Wl3 = (const float*)d_in[23]; const float* bl3 = (const float*)d_in[24];

    void* p;
    cudaGetSymbolAddress(&p, g_h0);        float* h0   = (float*)p;
    cudaGetSymbolAddress(&p, g_h1);        float* h1   = (float*)p;
    cudaGetSymbolAddress(&p, g_h2);        float* h2   = (float*)p;
    cudaGetSymbolAddress(&p, g_xw);        float* xw   = (float*)p;
    cudaGetSymbolAddress(&p, g_dis);       float* dis  = (float*)p;
    cudaGetSymbolAddress(&p, g_degI);      int* degI   = (int*)p;
    cudaGetSymbolAddress(&p, g_rowstart);  int* rowst  = (int*)p;
    cudaGetSymbolAddress(&p, g_cursor);    int* cursor = (int*)p;
    cudaGetSymbolAddress(&p, g_ecol);      int* ecol   = (int*)p;
    cudaGetSymbolAddress(&p, g_ctr);       int* ctr    = (int*)p;
    cudaGetSymbolAddress(&p, g_degPI);     int* degPI  = (int*)p;
    cudaGetSymbolAddress(&p, g_rowstartP); int* rowstP = (int*)p;
    cudaGetSymbolAddress(&p, g_cursorP);   int* cursP  = (int*)p;
    cudaGetSymbolAddress(&p, g_ecolP);     int* ecolP  = (int*)p;
    cudaGetSymbolAddress(&p, g_disP);      float* disP = (float*)p;
    cudaGetSymbolAddress(&p, g_xwP);       float* xwP  = (float*)p;
    cudaGetSymbolAddress(&p, g_hP);        float* hP   = (float*)p;

    static bool attr_done = false;
    if (!attr_done) {
        cudaFuncSetAttribute(gemm_tf32, cudaFuncAttributeMaxDynamicSharedMemorySize, GEMM_SMEM);
        cudaFuncSetAttribute(gemm_pool, cudaFuncAttributeMaxDynamicSharedMemorySize, GEMM_SMEM);
        attr_done = true;
    }

    // launches 1-3, then #4 = the big tf32 GEMM (ncu window lands on the 4th launch)
    zero_all_kernel<<<256, 256>>>();                                         // 1
    degi_kernel<<<E_ALL / 256, 256>>>(dst_all, degI, E_ALL);                 // 2
    assign_kernel<<<NTOT / 256, 256>>>(degI, rowst, cursor, dis, NTOT, ctr); // 3
    gemm_tf32<<<NTOT / 128, 256, GEMM_SMEM>>>(x, W1, xw, 128);               // 4  <-- profiled

    place_kernel<<<E_ALL / 256, 256>>>(src_all, dst_all, cursor, ecol, E_ALL);

    // ---- 3 GCN layers ----
    agg_kernel<<<NTOT / 8, 256>>>(xw, rowst, degI, ecol, dis, b1, h0, NTOT);
    gemm_tf32<<<NTOT / 128, 256, GEMM_SMEM>>>(h0, W2, xw, 128);
    agg_kernel<<<NTOT / 8, 256>>>(xw, rowst, degI, ecol, dis, b2, h1, NTOT);
    gemm_tf32<<<NTOT / 128, 256, GEMM_SMEM>>>(h1, W3, xw, 128);
    agg_kernel<<<NTOT / 8, 256>>>(xw, rowst, degI, ecol, dis, b3, h2, NTOT);

    // ---- dual attention pooling ----
    mean384_kernel<<<512, 384>>>();
    catt_kernel<<<128, 384>>>(Wg_att);
    alphagp_kernel<<<1024, 256>>>();
    pv_kernel<<<64, 768>>>(Wal, bal);
    pvnorm_kernel<<<128, 128>>>();

    // ---- CAG pool ----
    score_kernel<<<NTOT / 8, 256>>>();
    topk_kernel<<<128, 512>>>();

    // ---- pooled CSR (combined over both clusters, scan-free) ----
    degPI2_kernel<<<(2 * E_C) / 256, 256>>>(src_c[0], dst_c[0], src_c[1], dst_c[1]);
    assign_kernel<<<(2 * NPOOL) / 256, 256>>>(degPI, rowstP, cursP, disP, 2 * NPOOL, ctr + 1);
    placeP2_kernel<<<(2 * E_C) / 256, 256>>>(src_c[0], dst_c[0], src_c[1], dst_c[1]);

    // ---- pooled GCN: GEMM with fused gather + one agg ----
    gemm_pool<<<(2 * NPOOL) / 128, 256, GEMM_SMEM>>>(Wf, xwP);
    agg_kernel<<<(2 * NPOOL) / 8, 256>>>(xwP, rowstP, degPI, ecolP, disP, bf, hP, 2 * NPOOL);

    // ---- final attention pools + MLP head ----
    meanF_kernel<<<256, 128>>>();
    cF_kernel<<<128, 128>>>(Wg_fin);
    alphagfin_kernel<<<512, 256>>>();
    mlp_kernel<<<64, 128>>>(Wl1, bl1, Wl2, bl2, Wl3, bl3, (float*)d_out);
}

// round 15
// speedup vs baseline: 1.3254x; 1.1220x over previous
#include <cuda_runtime.h>
#include <cuda_bf16.h>
#include <math.h>
#include <stdint.h>

// Problem constants
#define B_      64
#define N1_     512
#define N2_     512
#define NPER    1024
#define NTOT    65536
#define KSEL    256
#define NPOOL   16384
#define E_ALL   1048576
#define E_C     524288

// ---------------- scratch ----------------
__device__ float g_h0[(size_t)NTOT * 128];
__device__ float g_h1[(size_t)NTOT * 128];
__device__ float g_h2[(size_t)NTOT * 128];
__device__ float g_xw[(size_t)NTOT * 128];
__device__ float g_dis[NTOT];

// CSR for the big graph
__device__ int g_degI[NTOT];
__device__ int g_rowstart[NTOT];
__device__ int g_cursor[NTOT];
__device__ int g_ecol[E_ALL];
__device__ int g_ctr[2];

__device__ float g_mean[128 * 384];
__device__ float g_catt[128 * 384];
__device__ float g_gp[128 * 384];
__device__ float g_pv[64 * 768];
__device__ float g_pvnorm[128];

__device__ float g_score[2][B_ * N1_];
__device__ int   g_map[2][B_ * N1_];
__device__ int   g_perm[2][B_ * KSEL];

// pooled CSR (combined over both clusters)
__device__ int   g_degPI[2 * NPOOL];
__device__ int   g_rowstartP[2 * NPOOL];
__device__ int   g_cursorP[2 * NPOOL];
__device__ int   g_ecolP[2 * E_C];
__device__ float g_disP[2 * NPOOL];

__device__ float g_xwP[(size_t)2 * NPOOL * 128];
__device__ float g_hP[2][(size_t)NPOOL * 128];

__device__ float g_meanF[2][B_ * 128];
__device__ float g_cF[2][B_ * 128];
__device__ float g_gfin[2][B_ * 128];

__device__ __forceinline__ float xcat_at(int node, int f) {
    const float* H = (f < 128) ? g_h0 : ((f < 256) ? g_h1 : g_h2);
    return H[(size_t)node * 128 + (f & 127)];
}
__device__ __forceinline__ float sigmoidf_(float x) { return 1.f / (1.f + expf(-x)); }

// ---------------- zero everything that accumulates ----------------
__global__ void zero_all_kernel() {
    const int NM = 128 * 384;
    int stride = gridDim.x * blockDim.x;
    for (int i = blockIdx.x * blockDim.x + threadIdx.x;
         i < NTOT + 2 * NPOOL + 2 + 2 * NM + 2 * 2 * B_ * 128; i += stride) {
        int j = i;
        if (j < NTOT) { g_degI[j] = 0; continue; }
        j -= NTOT;
        if (j < 2 * NPOOL) { g_degPI[j] = 0; continue; }
        j -= 2 * NPOOL;
        if (j < 2) { g_ctr[j] = 0; continue; }
        j -= 2;
        if (j < NM) { g_mean[j] = 0.f; continue; }
        j -= NM;
        if (j < NM) { g_gp[j] = 0.f; continue; }
        j -= NM;
        if (j < 2 * B_ * 128) { ((float*)g_meanF)[j] = 0.f; continue; }
        j -= 2 * B_ * 128;
        ((float*)g_gfin)[j] = 0.f;
    }
}

__global__ void degi_kernel(const int* __restrict__ dst, int* __restrict__ deg, int E) {
    int e = blockIdx.x * blockDim.x + threadIdx.x;
    if (e < E) atomicAdd(&deg[dst[e]], 1);
}

// combined pooled degree count over both clusters
__global__ void degPI2_kernel(const int* __restrict__ src0, const int* __restrict__ dst0,
                              const int* __restrict__ src1, const int* __restrict__ dst1) {
    int e = blockIdx.x * blockDim.x + threadIdx.x;
    if (e < E_C) {
        int r = g_map[0][src0[e]], c = g_map[0][dst0[e]];
        if (r >= 0 && c >= 0) atomicAdd(&g_degPI[c], 1);
    } else {
        e -= E_C;
        int r = g_map[1][src1[e]], c = g_map[1][dst1[e]];
        if (r >= 0 && c >= 0) atomicAdd(&g_degPI[NPOOL + c], 1);
    }
}

// rowstart assignment without scans: order-free atomic range grab.
__global__ void assign_kernel(const int* __restrict__ deg, int* __restrict__ rowstart,
                              int* __restrict__ cursor, float* __restrict__ dis,
                              int n, int* __restrict__ ctr) {
    int i = blockIdx.x * blockDim.x + threadIdx.x;
    if (i >= n) return;
    int d = deg[i];
    int rs = atomicAdd(ctr, d);
    rowstart[i] = rs;
    cursor[i] = rs;
    dis[i] = rsqrtf((float)d + 1.f);
}

// ---------------- CSR edge placement (cursor pre-seeded with rowstart) ----------------
__global__ void place_kernel(const int* __restrict__ src, const int* __restrict__ dst,
                             int* __restrict__ cursor, int* __restrict__ ecol, int E) {
    int e = blockIdx.x * blockDim.x + threadIdx.x;
    if (e >= E) return;
    int pos = atomicAdd(&cursor[dst[e]], 1);
    ecol[pos] = src[e];
}
// combined pooled placement over both clusters
__global__ void placeP2_kernel(const int* __restrict__ src0, const int* __restrict__ dst0,
                               const int* __restrict__ src1, const int* __restrict__ dst1) {
    int e = blockIdx.x * blockDim.x + threadIdx.x;
    int cl = 0, off = 0;
    const int* S = src0;
    const int* D = dst0;
    if (e >= E_C) { e -= E_C; S = src1; D = dst1; cl = 1; off = NPOOL; }
    int r = g_map[cl][S[e]], c = g_map[cl][D[e]];
    if (r < 0 || c < 0) return;
    int pos = atomicAdd(&g_cursorP[c + off], 1);
    g_ecolP[pos] = r + off;
}

// ============ 3xBF16 tensor-core GEMM (m16n8k16, hi/lo split, double-buffered) ============
// x = hi + lo (both bf16); acc += aL*bH + aH*bL + aH*bH  (~2^-16 effective input precision)
__device__ __forceinline__ void mma_bf16(float* c, const uint32_t* a, uint32_t b0, uint32_t b1) {
    asm volatile("mma.sync.aligned.m16n8k16.row.col.f32.bf16.bf16.f32 "
                 "{%0,%1,%2,%3}, {%4,%5,%6,%7}, {%8,%9}, {%0,%1,%2,%3};"
                 : "+f"(c[0]), "+f"(c[1]), "+f"(c[2]), "+f"(c[3])
                 : "r"(a[0]), "r"(a[1]), "r"(a[2]), "r"(a[3]), "r"(b0), "r"(b1));
}

// pack a k-pair (x = k, y = k+1) into hi-plane and lo-plane bf16x2 words
__device__ __forceinline__ void split2_bf16(float x, float y, uint32_t& hi, uint32_t& lo) {
    __nv_bfloat16 xh = __float2bfloat16(x);
    __nv_bfloat16 yh = __float2bfloat16(y);
    __nv_bfloat16 xl = __float2bfloat16(x - __bfloat162float(xh));
    __nv_bfloat16 yl = __float2bfloat16(y - __bfloat162float(yh));
    hi = ((uint32_t)__bfloat16_as_ushort(yh) << 16) | (uint32_t)__bfloat16_as_ushort(xh);
    lo = ((uint32_t)__bfloat16_as_ushort(yl) << 16) | (uint32_t)__bfloat16_as_ushort(xl);
}

// smem layout (words = uint32):
//   A plane: 128 rows x STA (16 kpairs + 4 pad); STA % 32 == 20 -> frag banks 20r+kp all distinct
//   B plane: 16 kpair-rows x STB (128 cols + 8 pad); STB % 32 == 8 -> frag banks 8kp+n distinct
#define STA 20
#define STB 136
#define A_PLANE (128 * STA)
#define B_PLANE (16 * STB)
#define BUF_WORDS (2 * A_PLANE + 2 * B_PLANE)   // 9472 words = 37888 B
#define GEMM_SMEM (2 * BUF_WORDS * 4)           // 75776 B (double buffered)

__device__ __forceinline__ void ldgA_dense(const float* __restrict__ A, int K, int R0, int k0,
                                           int tid, float4* ra) {
#pragma unroll
    for (int i = 0; i < 4; i++) {
        int q = tid + i * 256;
        int r = q >> 3, c4 = (q & 7) << 2;
        ra[i] = *(const float4*)(A + (size_t)(R0 + r) * K + k0 + c4);
    }
}
__device__ __forceinline__ void ldgB(const float* __restrict__ W, int k0, int tid,
                                     float2* rb0, float2* rb1) {
#pragma unroll
    for (int i = 0; i < 4; i++) {
        int Q = tid + i * 256;
        int kp = Q >> 6;
        int c2 = (Q & 63) << 1;
        rb0[i] = *(const float2*)(W + (size_t)(k0 + 2 * kp) * 128 + c2);
        rb1[i] = *(const float2*)(W + (size_t)(k0 + 2 * kp + 1) * 128 + c2);
    }
}

__device__ __forceinline__ void sts_buf(float* buf, int tid, const float4* ra,
                                        const float2* rb0, const float2* rb1) {
    uint32_t* AsH = (uint32_t*)buf;
    uint32_t* AsL = AsH + A_PLANE;
    uint32_t* BsH = AsL + A_PLANE;
    uint32_t* BsL = BsH + B_PLANE;
#pragma unroll
    for (int i = 0; i < 4; i++) {
        int q = tid + i * 256;
        int r = q >> 3, kp0 = (q & 7) << 1;
        uint32_t h0, l0, h1, l1;
        split2_bf16(ra[i].x, ra[i].y, h0, l0);
        split2_bf16(ra[i].z, ra[i].w, h1, l1);
        AsH[r * STA + kp0]     = h0;
        AsH[r * STA + kp0 + 1] = h1;
        AsL[r * STA + kp0]     = l0;
        AsL[r * STA + kp0 + 1] = l1;
    }
#pragma unroll
    for (int i = 0; i < 4; i++) {
        int Q = tid + i * 256;
        int kp = Q >> 6, c2 = (Q & 63) << 1;
        uint32_t h0, l0, h1, l1;
        split2_bf16(rb0[i].x, rb1[i].x, h0, l0);   // col c2:   (k, k+1)
        split2_bf16(rb0[i].y, rb1[i].y, h1, l1);   // col c2+1: (k, k+1)
        BsH[kp * STB + c2]     = h0;
        BsH[kp * STB + c2 + 1] = h1;
        BsL[kp * STB + c2]     = l0;
        BsL[kp * STB + c2 + 1] = l1;
    }
}

__device__ __forceinline__ void compute_buf(const float* buf, int lane, int mw, int nw,
                                            float c[2][8][4]) {
    const uint32_t* AsH = (const uint32_t*)buf;
    const uint32_t* AsL = AsH + A_PLANE;
    const uint32_t* BsH = AsL + A_PLANE;
    const uint32_t* BsL = BsH + B_PLANE;
#pragma unroll
    for (int step = 0; step < 2; step++) {
        int kpb = step * 8 + (lane & 3);
        uint32_t aH[2][4], aL[2][4];
#pragma unroll
        for (int mi = 0; mi < 2; mi++) {
            int r = mw * 32 + mi * 16 + (lane >> 2);
            int o0 = r * STA + kpb, o1 = (r + 8) * STA + kpb;
            aH[mi][0] = AsH[o0];     aH[mi][1] = AsH[o1];
            aH[mi][2] = AsH[o0 + 4]; aH[mi][3] = AsH[o1 + 4];
            aL[mi][0] = AsL[o0];     aL[mi][1] = AsL[o1];
            aL[mi][2] = AsL[o0 + 4]; aL[mi][3] = AsL[o1 + 4];
        }
#pragma unroll
        for (int ni = 0; ni < 8; ni++) {
            int n = nw * 64 + ni * 8 + (lane >> 2);
            int ob0 = kpb * STB + n, ob1 = (kpb + 4) * STB + n;
            uint32_t bH0 = BsH[ob0], bH1 = BsH[ob1];
            uint32_t bL0 = BsL[ob0], bL1 = BsL[ob1];
            mma_bf16(c[0][ni], aL[0], bH0, bH1);
            mma_bf16(c[1][ni], aL[1], bH0, bH1);
            mma_bf16(c[0][ni], aH[0], bL0, bL1);
            mma_bf16(c[1][ni], aH[1], bL0, bL1);
            mma_bf16(c[0][ni], aH[0], bH0, bH1);
            mma_bf16(c[1][ni], aH[1], bH0, bH1);
        }
    }
}

__device__ __forceinline__ void gemm_epilogue(int lane, int mw, int nw, int R0,
                                              float c[2][8][4], float* __restrict__ C)
{
#pragma unroll
    for (int mi = 0; mi < 2; mi++) {
#pragma unroll
        for (int ni = 0; ni < 8; ni++) {
            int row = R0 + mw * 32 + mi * 16 + (lane >> 2);
            int col = nw * 64 + ni * 8 + 2 * (lane & 3);
            *(float2*)(C + (size_t)row * 128 + col) = make_float2(c[mi][ni][0], c[mi][ni][1]);
            *(float2*)(C + (size_t)(row + 8) * 128 + col) = make_float2(c[mi][ni][2], c[mi][ni][3]);
        }
    }
}

__global__ void __launch_bounds__(256, 2) gemm_bf16(
    const float* __restrict__ A, const float* __restrict__ W,
    float* __restrict__ C, int K)
{
    extern __shared__ float sm[];
    int tid = threadIdx.x, lane = tid & 31, w = tid >> 5;
    int mw = w >> 1, nw = w & 1;
    int R0 = blockIdx.x * 128;

    float c[2][8][4];
#pragma unroll
    for (int mi = 0; mi < 2; mi++)
#pragma unroll
        for (int ni = 0; ni < 8; ni++)
#pragma unroll
            for (int k = 0; k < 4; k++) c[mi][ni][k] = 0.f;

    float4 ra[4];
    float2 rb0[4], rb1[4];
    ldgA_dense(A, K, R0, 0, tid, ra);
    ldgB(W, 0, tid, rb0, rb1);
    sts_buf(sm, tid, ra, rb0, rb1);

    int nch = K >> 5;
    for (int ch = 0; ch < nch; ch++) {
        __syncthreads();
        if (ch + 1 < nch) {
            ldgA_dense(A, K, R0, (ch + 1) << 5, tid, ra);
            ldgB(W, (ch + 1) << 5, tid, rb0, rb1);
        }
        compute_buf(sm + (ch & 1) * BUF_WORDS, lane, mw, nw, c);
        if (ch + 1 < nch)
            sts_buf(sm + ((ch + 1) & 1) * BUF_WORDS, tid, ra, rb0, rb1);
    }
    gemm_epilogue(lane, mw, nw, R0, c, C);
}

// ---- pooled GEMM with fused gather: A[row][k] = xcat(node(row),k) * gate(row); K=384 ----
__global__ void __launch_bounds__(256, 2) gemm_pool(
    const float* __restrict__ W, float* __restrict__ C)
{
    extern __shared__ float sm[];
    int tid = threadIdx.x, lane = tid & 31, w = tid >> 5;
    int mw = w >> 1, nw = w & 1;
    int R0 = blockIdx.x * 128;

    const float* Hs[3] = { g_h0, g_h1, g_h2 };
    int nodeR[4];
    float gateR[4];
#pragma unroll
    for (int i = 0; i < 4; i++) {
        int q = tid + i * 256;
        int r = q >> 3;
        int row = R0 + r;
        int cl = row >> 14;
        int rr = row & (NPOOL - 1);
        int g = rr >> 8;
        int j = g_perm[cl][rr];
        nodeR[i] = g * NPER + cl * N1_ + j;
        gateR[i] = sigmoidf_(g_score[cl][g * 512 + j]);
    }

    float c[2][8][4];
#pragma unroll
    for (int mi = 0; mi < 2; mi++)
#pragma unroll
        for (int ni = 0; ni < 8; ni++)
#pragma unroll
            for (int k = 0; k < 4; k++) c[mi][ni][k] = 0.f;

    float4 ra[4];
    float2 rb0[4], rb1[4];
    auto ldgA_pool = [&](int k0) {
        const float* H = Hs[k0 >> 7];
        int kloc = k0 & 127;
#pragma unroll
        for (int i = 0; i < 4; i++) {
            int q = tid + i * 256;
            int c4 = (q & 7) << 2;
            float4 v = *(const float4*)(H + (size_t)nodeR[i] * 128 + kloc + c4);
            float gt = gateR[i];
            v.x *= gt; v.y *= gt; v.z *= gt; v.w *= gt;
            ra[i] = v;
        }
    };

    ldgA_pool(0);
    ldgB(W, 0, tid, rb0, rb1);
    sts_buf(sm, tid, ra, rb0, rb1);

    const int nch = 384 >> 5;   // 12
    for (int ch = 0; ch < nch; ch++) {
        __syncthreads();
        if (ch + 1 < nch) {
            ldgA_pool((ch + 1) << 5);
            ldgB(W, (ch + 1) << 5, tid, rb0, rb1);
        }
        compute_buf(sm + (ch & 1) * BUF_WORDS, lane, mw, nw, c);
        if (ch + 1 < nch)
            sts_buf(sm + ((ch + 1) & 1) * BUF_WORDS, tid, ra, rb0, rb1);
    }
    gemm_epilogue(lane, mw, nw, R0, c, C);
}

// ---------------- CSR gather-aggregate + self loop + bias + relu (4-way unrolled) ----------------
__global__ void __launch_bounds__(256) agg_kernel(
    const float* __restrict__ xw,
    const int* __restrict__ rowstart, const int* __restrict__ degI,
    const int* __restrict__ ecol, const float* __restrict__ dis,
    const float* __restrict__ bias, float* __restrict__ out, int n)
{
    int w = (blockIdx.x * blockDim.x + threadIdx.x) >> 5;
    if (w >= n) return;
    int lane = threadIdx.x & 31;
    int rs = rowstart[w];
    int re = rs + degI[w];
    float4 a0 = make_float4(0.f, 0.f, 0.f, 0.f);
    float4 a1 = make_float4(0.f, 0.f, 0.f, 0.f);
    float4 a2 = make_float4(0.f, 0.f, 0.f, 0.f);
    float4 a3 = make_float4(0.f, 0.f, 0.f, 0.f);
    int i = rs;
    for (; i + 4 <= re; i += 4) {
        int s0 = ecol[i], s1 = ecol[i + 1], s2 = ecol[i + 2], s3 = ecol[i + 3];
        float w0 = dis[s0], w1 = dis[s1], w2 = dis[s2], w3 = dis[s3];
        float4 v0 = *(const float4*)(xw + (size_t)s0 * 128 + lane * 4);
        float4 v1 = *(const float4*)(xw + (size_t)s1 * 128 + lane * 4);
        float4 v2 = *(const float4*)(xw + (size_t)s2 * 128 + lane * 4);
        float4 v3 = *(const float4*)(xw + (size_t)s3 * 128 + lane * 4);
        a0.x = fmaf(v0.x, w0, a0.x); a0.y = fmaf(v0.y, w0, a0.y);
        a0.z = fmaf(v0.z, w0, a0.z); a0.w = fmaf(v0.w, w0, a0.w);
        a1.x = fmaf(v1.x, w1, a1.x); a1.y = fmaf(v1.y, w1, a1.y);
        a1.z = fmaf(v1.z, w1, a1.z); a1.w = fmaf(v1.w, w1, a1.w);
        a2.x = fmaf(v2.x, w2, a2.x); a2.y = fmaf(v2.y, w2, a2.y);
        a2.z = fmaf(v2.z, w2, a2.z); a2.w = fmaf(v2.w, w2, a2.w);
        a3.x = fmaf(v3.x, w3, a3.x); a3.y = fmaf(v3.y, w3, a3.y);
        a3.z = fmaf(v3.z, w3, a3.z); a3.w = fmaf(v3.w, w3, a3.w);
    }
    for (; i < re; i++) {
        int s0 = ecol[i];
        float w0 = dis[s0];
        float4 v0 = *(const float4*)(xw + (size_t)s0 * 128 + lane * 4);
        a0.x = fmaf(v0.x, w0, a0.x); a0.y = fmaf(v0.y, w0, a0.y);
        a0.z = fmaf(v0.z, w0, a0.z); a0.w = fmaf(v0.w, w0, a0.w);
    }
    a0.x += a1.x + a2.x + a3.x;
    a0.y += a1.y + a2.y + a3.y;
    a0.z += a1.z + a2.z + a3.z;
    a0.w += a1.w + a2.w + a3.w;
    float dd = dis[w];
    float sw = dd * dd;
    float4 self = *(const float4*)(xw + (size_t)w * 128 + lane * 4);
    float4 r;
    r.x = fmaxf(fmaf(a0.x, dd, fmaf(self.x, sw, bias[lane * 4 + 0])), 0.f);
    r.y = fmaxf(fmaf(a0.y, dd, fmaf(self.y, sw, bias[lane * 4 + 1])), 0.f);
    r.z = fmaxf(fmaf(a0.z, dd, fmaf(self.z, sw, bias[lane * 4 + 2])), 0.f);
    r.w = fmaxf(fmaf(a0.w, dd, fmaf(self.w, sw, bias[lane * 4 + 3])), 0.f);
    *(float4*)(out + (size_t)w * 128 + lane * 4) = r;
}

// ---------------- attention pool (big, 384 feats) ----------------
__global__ void mean384_kernel() {
    int s = blockIdx.x >> 2, ch = blockIdx.x & 3;
    int f = threadIdx.x;
    int g = s & 63, cl = s >> 6;
    int base = g * NPER + cl * N1_ + ch * 128;
    float acc = 0.f;
#pragma unroll 4
    for (int j = 0; j < 128; j++) acc += xcat_at(base + j, f);
    atomicAdd(&g_mean[s * 384 + f], acc);
}

__global__ void catt_kernel(const float* __restrict__ Wg) {
    __shared__ float m[384];
    int s = blockIdx.x, f = threadIdx.x;
    m[f] = g_mean[s * 384 + f] * (1.f / 512.f);
    __syncthreads();
    float acc = 0.f;
    for (int k = 0; k < 384; k++) acc = fmaf(m[k], Wg[k * 384 + f], acc);
    g_catt[s * 384 + f] = tanhf(acc);
}

// fused alpha + gp: one xcat pass.
__global__ void __launch_bounds__(256) alphagp_kernel() {
    int blk = blockIdx.x;
    int s = blk >> 3, ch = blk & 7;
    int g = s & 63, cl = s >> 6;
    int base = g * NPER + cl * N1_ + ch * 64;
    int wid = threadIdx.x >> 5, lane = threadIdx.x & 31;
    __shared__ float csh[384];
    __shared__ float gpsh[384];
    for (int t = threadIdx.x; t < 384; t += 256) { csh[t] = g_catt[s * 384 + t]; gpsh[t] = 0.f; }
    __syncthreads();
    float acc[12];
#pragma unroll
    for (int q = 0; q < 12; q++) acc[q] = 0.f;
    for (int j = 0; j < 8; j++) {
        int node = base + wid * 8 + j;
        float xv[12];
        float dot = 0.f;
#pragma unroll
        for (int q = 0; q < 12; q++) {
            int f = q * 32 + lane;
            xv[q] = xcat_at(node, f);
            dot = fmaf(xv[q], csh[f], dot);
        }
#pragma unroll
        for (int o = 16; o; o >>= 1) dot += __shfl_xor_sync(0xffffffffu, dot, o);
        float alpha = sigmoidf_(dot);
#pragma unroll
        for (int q = 0; q < 12; q++) acc[q] = fmaf(xv[q], alpha, acc[q]);
    }
#pragma unroll
    for (int q = 0; q < 12; q++) atomicAdd(&gpsh[q * 32 + lane], acc[q]);
    __syncthreads();
    for (int t = threadIdx.x; t < 384; t += 256) atomicAdd(&g_gp[s * 384 + t], gpsh[t]);
}

__global__ void pv_kernel(const float* __restrict__ Wal, const float* __restrict__ bal) {
    __shared__ float in[768];
    int g = blockIdx.x, t = threadIdx.x;
    in[t] = (t < 384) ? g_gp[g * 384 + t] : g_gp[(64 + g) * 384 + (t - 384)];
    __syncthreads();
    float acc = bal[t];
    for (int k = 0; k < 768; k++) acc = fmaf(in[k], Wal[k * 768 + t], acc);
    g_pv[g * 768 + t] = acc;
}

__global__ void pvnorm_kernel() {
    int b = blockIdx.x;
    int cl = b >> 6, g = b & 63;
    int t = threadIdx.x;
    float acc = 0.f;
    for (int k = t; k < 384; k += 128) {
        float v = g_pv[g * 768 + cl * 384 + k];
        acc += v * v;
    }
    __shared__ float red[128];
    red[t] = acc;
    __syncthreads();
    for (int o = 64; o; o >>= 1) {
        if (t < o) red[t] += red[t + o];
        __syncthreads();
    }
    if (!t) g_pvnorm[b] = sqrtf(red[0]);
}

// ---------------- CAG pool ----------------
__global__ void score_kernel() {
    int w = (blockIdx.x * blockDim.x + threadIdx.x) >> 5;
    if (w >= NTOT) return;
    int lane = threadIdx.x & 31;
    int cl = w >> 15;
    int rem = w & 32767;
    int g = rem >> 9, j = rem & 511;
    int node = g * NPER + cl * N1_ + j;
    const float* q = g_pv + g * 768 + cl * 384;
    float acc = 0.f;
    for (int t = lane; t < 384; t += 32) acc += xcat_at(node, t) * q[t];
#pragma unroll
    for (int o = 16; o; o >>= 1) acc += __shfl_xor_sync(0xffffffffu, acc, o);
    if (!lane) g_score[cl][g * 512 + j] = acc / g_pvnorm[cl * 64 + g];
}

__global__ void topk_kernel() {
    int b = blockIdx.x;
    int cl = b >> 6, g = b & 63;
    int j = threadIdx.x;
    __shared__ float s[512];
    s[j] = g_score[cl][g * 512 + j];
    __syncthreads();
    float mys = s[j];
    int rank = 0;
    for (int i = 0; i < 512; i++) {
        float o = s[i];
        rank += (o > mys) || (o == mys && i < j);
    }
    g_map[cl][g * 512 + j] = (rank < KSEL) ? (g * KSEL + rank) : -1;
    if (rank < KSEL) g_perm[cl][g * KSEL + rank] = j;
}

// ---------------- final attention pool ----------------
__global__ void meanF_kernel() {
    int b = blockIdx.x >> 1, ch = blockIdx.x & 1;
    int cl = b >> 6, g = b & 63;
    int f = threadIdx.x;
    const float* h = g_hP[cl] + ((size_t)g * KSEL + ch * 128) * 128;
    float acc = 0.f;
#pragma unroll 4
    for (int j = 0; j < 128; j++) acc += h[(size_t)j * 128 + f];
    atomicAdd(&g_meanF[cl][g * 128 + f], acc);
}

__global__ void cF_kernel(const float* __restrict__ Wg) {
    int b = blockIdx.x;
    int cl = b >> 6, g = b & 63;
    int f = threadIdx.x;
    __shared__ float m[128];
    m[f] = g_meanF[cl][g * 128 + f] * (1.f / 256.f);
    __syncthreads();
    float acc = 0.f;
    for (int k = 0; k < 128; k++) acc = fmaf(m[k], Wg[k * 128 + f], acc);
    g_cF[cl][g * 128 + f] = tanhf(acc);
}

// fused alphaP + gfin: one hP pass.
__global__ void __launch_bounds__(256) alphagfin_kernel() {
    int blk = blockIdx.x;
    int cl = blk >> 8;
    int within = blk & 255;
    int g = within >> 2, ch = within & 3;
    int baseRow = g * KSEL + ch * 64;
    int wid = threadIdx.x >> 5, lane = threadIdx.x & 31;
    __shared__ float csh[128];
    __shared__ float accsh[128];
    if (threadIdx.x < 128) {
        csh[threadIdx.x] = g_cF[cl][g * 128 + threadIdx.x];
        accsh[threadIdx.x] = 0.f;
    }
    __syncthreads();
    float acc[4];
#pragma unroll
    for (int q = 0; q < 4; q++) acc[q] = 0.f;
    for (int j = 0; j < 8; j++) {
        int row = baseRow + wid * 8 + j;
        const float* h = g_hP[cl] + (size_t)row * 128;
        float hv[4];
        float dot = 0.f;
#pragma unroll
        for (int q = 0; q < 4; q++) {
            int f = q * 32 + lane;
            hv[q] = h[f];
            dot = fmaf(hv[q], csh[f], dot);
        }
#pragma unroll
        for (int o = 16; o; o >>= 1) dot += __shfl_xor_sync(0xffffffffu, dot, o);
        float alpha = sigmoidf_(dot);
#pragma unroll
        for (int q = 0; q < 4; q++) acc[q] = fmaf(hv[q], alpha, acc[q]);
    }
#pragma unroll
    for (int q = 0; q < 4; q++) atomicAdd(&accsh[q * 32 + lane], acc[q]);
    __syncthreads();
    if (threadIdx.x < 128) atomicAdd(&g_gfin[cl][g * 128 + threadIdx.x], accsh[threadIdx.x]);
}

// ---------------- final MLP ----------------
__global__ void mlp_kernel(const float* __restrict__ Wl1, const float* __restrict__ bl1,
                           const float* __restrict__ Wl2, const float* __restrict__ bl2,
                           const float* __restrict__ Wl3, const float* __restrict__ bl3,
                           float* __restrict__ out)
{
    __shared__ float in[256];
    __shared__ float z1[128];
    __shared__ float z2[64];
    int g = blockIdx.x, t = threadIdx.x;
    in[t] = g_gfin[0][g * 128 + t];
    in[128 + t] = g_gfin[1][g * 128 + t];
    __syncthreads();
    float a = bl1[t];
    for (int k = 0; k < 256; k++) a = fmaf(in[k], Wl1[k * 128 + t], a);
    z1[t] = fmaxf(a, 0.f);
    __syncthreads();
    if (t < 64) {
        float a2 = bl2[t];
        for (int k = 0; k < 128; k++) a2 = fmaf(z1[k], Wl2[k * 64 + t], a2);
        z2[t] = fmaxf(a2, 0.f);
    }
    __syncthreads();
    if (t < 2) {
        float a3 = bl3[t];
        for (int k = 0; k < 64; k++) a3 = fmaf(z2[k], Wl3[k * 2 + t], a3);
        out[g * 2 + t] = a3;
    }
}

// ---------------- host orchestration (single stream, graph-capture safe) ----------------
extern "C" void kernel_launch(void* const* d_in, const int* in_sizes, int n_in,
                              void* d_out, int out_size)
{
    const float* x       = (const float*)d_in[0];
    const int*   src_all = (const int*)d_in[1];
    const int*   dst_all = (const int*)d_in[2];
    const int*   src_c[2] = { (const int*)d_in[3], (const int*)d_in[5] };
    const int*   dst_c[2] = { (const int*)d_in[4], (const int*)d_in[6] };
    const float* W1 = (const float*)d_in[7];  const float* b1 = (const float*)d_in[8];
    const float* W2 = (const float*)d_in[9];  const float* b2 = (const float*)d_in[10];
    const float* W3 = (const float*)d_in[11]; const float* b3 = (const float*)d_in[12];
    const float* Wg_att = (const float*)d_in[13];
    const float* Wal = (const float*)d_in[14]; const float* bal = (const float*)d_in[15];
    const float* Wf  = (const float*)d_in[16]; const float* bf  = (const float*)d_in[17];
    const float* Wg_fin = (const float*)d_in[18];
    const float* Wl1 = (const float*)d_in[19]; const float* bl1 = (const float*)d_in[20];
    const float* Wl2 = (const float*)d_in[21]; const float* bl2 = (const float*)d_in[22];
    const float* Wl3 = (const float*)d_in[23]; const float* bl3 = (const float*)d_in[24];

    void* p;
    cudaGetSymbolAddress(&p, g_h0);        float* h0   = (float*)p;
    cudaGetSymbolAddress(&p, g_h1);        float* h1   = (float*)p;
    cudaGetSymbolAddress(&p, g_h2);        float* h2   = (float*)p;
    cudaGetSymbolAddress(&p, g_xw);        float* xw   = (float*)p;
    cudaGetSymbolAddress(&p, g_dis);       float* dis  = (float*)p;
    cudaGetSymbolAddress(&p, g_degI);      int* degI   = (int*)p;
    cudaGetSymbolAddress(&p, g_rowstart);  int* rowst  = (int*)p;
    cudaGetSymbolAddress(&p, g_cursor);    int* cursor = (int*)p;
    cudaGetSymbolAddress(&p, g_ecol);      int* ecol   = (int*)p;
    cudaGetSymbolAddress(&p, g_ctr);       int* ctr    = (int*)p;
    cudaGetSymbolAddress(&p, g_degPI);     int* degPI  = (int*)p;
    cudaGetSymbolAddress(&p, g_rowstartP); int* rowstP = (int*)p;
    cudaGetSymbolAddress(&p, g_cursorP);   int* cursP  = (int*)p;
    cudaGetSymbolAddress(&p, g_ecolP);     int* ecolP  = (int*)p;
    cudaGetSymbolAddress(&p, g_disP);      float* disP = (float*)p;
    cudaGetSymbolAddress(&p, g_xwP);       float* xwP  = (float*)p;
    cudaGetSymbolAddress(&p, g_hP);        float* hP   = (float*)p;

    static bool attr_done = false;
    if (!attr_done) {
        cudaFuncSetAttribute(gemm_bf16, cudaFuncAttributeMaxDynamicSharedMemorySize, GEMM_SMEM);
        cudaFuncSetAttribute(gemm_pool, cudaFuncAttributeMaxDynamicSharedMemorySize, GEMM_SMEM);
        attr_done = true;
    }

    // launches 1-3, then #4 = the big GEMM (ncu window lands on the 4th launch)
    zero_all_kernel<<<256, 256>>>();                                         // 1
    degi_kernel<<<E_ALL / 256, 256>>>(dst_all, degI, E_ALL);                 // 2
    assign_kernel<<<NTOT / 256, 256>>>(degI, rowst, cursor, dis, NTOT, ctr); // 3
    gemm_bf16<<<NTOT / 128, 256, GEMM_SMEM>>>(x, W1, xw, 128);               // 4  <-- profiled

    place_kernel<<<E_ALL / 256, 256>>>(src_all, dst_all, cursor, ecol, E_ALL);

    // ---- 3 GCN layers ----
    agg_kernel<<<NTOT / 8, 256>>>(xw, rowst, degI, ecol, dis, b1, h0, NTOT);
    gemm_bf16<<<NTOT / 128, 256, GEMM_SMEM>>>(h0, W2, xw, 128);
    agg_kernel<<<NTOT / 8, 256>>>(xw, rowst, degI, ecol, dis, b2, h1, NTOT);
    gemm_bf16<<<NTOT / 128, 256, GEMM_SMEM>>>(h1, W3, xw, 128);
    agg_kernel<<<NTOT / 8, 256>>>(xw, rowst, degI, ecol, dis, b3, h2, NTOT);

    // ---- dual attention pooling ----
    mean384_kernel<<<512, 384>>>();
    catt_kernel<<<128, 384>>>(Wg_att);
    alphagp_kernel<<<1024, 256>>>();
    pv_kernel<<<64, 768>>>(Wal, bal);
    pvnorm_kernel<<<128, 128>>>();

    // ---- CAG pool ----
    score_kernel<<<NTOT / 8, 256>>>();
    topk_kernel<<<128, 512>>>();

    // ---- pooled CSR (combined over both clusters, scan-free) ----
    degPI2_kernel<<<(2 * E_C) / 256, 256>>>(src_c[0], dst_c[0], src_c[1], dst_c[1]);
    assign_kernel<<<(2 * NPOOL) / 256, 256>>>(degPI, rowstP, cursP, disP, 2 * NPOOL, ctr + 1);
    placeP2_kernel<<<(2 * E_C) / 256, 256>>>(src_c[0], dst_c[0], src_c[1], dst_c[1]);

    // ---- pooled GCN: GEMM with fused gather + one agg ----
    gemm_pool<<<(2 * NPOOL) / 128, 256, GEMM_SMEM>>>(Wf, xwP);
    agg_kernel<<<(2 * NPOOL) / 8, 256>>>(xwP, rowstP, degPI, ecolP, disP, bf, hP, 2 * NPOOL);

    // ---- final attention pools + MLP head ----
    meanF_kernel<<<256, 128>>>();
    cF_kernel<<<128, 128>>>(Wg_fin);
    alphagfin_kernel<<<512, 256>>>();
    mlp_kernel<<<64, 128>>>(Wl1, bl1, Wl2, bl2, Wl3, bl3, (float*)d_out);
}